// round 6
// baseline (speedup 1.0000x reference)
#include <cuda_runtime.h>
#include <cuda_bf16.h>
#include <math.h>

// Problem constants (static per reference).
#define NN   50000
#define EE   800000
#define FEA  256
#define HID  256
#define CLS  64
#define THETA 0.5f

// ---------------- device scratch (no allocs allowed) ----------------
__device__ int    g_deg[NN];
__device__ float  g_dinv[NN];
__device__ int    g_rowptr[NN + 1];
__device__ int    g_cursor[NN];
__device__ int    g_ecol[EE];                // CSR column indices
__device__ float  g_h  [(size_t)NN * HID];   // h = x @ W (current layer)
__device__ float  g_x1 [(size_t)NN * HID];   // relu'd conv1 output
__device__ double g_pos_loss;
__device__ double g_neg_loss;
__device__ unsigned long long g_pos_cnt;
__device__ unsigned long long g_neg_cnt;

// ---------------- degree ----------------
__global__ void k_deg_count(const int* __restrict__ row, int e) {
    int i = blockIdx.x * blockDim.x + threadIdx.x;
    if (i < e) atomicAdd(&g_deg[row[i]], 1);
}

// ---------------- single-block scan over g_deg -> g_rowptr, g_cursor, g_dinv ----------------
__global__ void k_scan(int n) {
    const int T = 1024;
    const int C = (NN + T - 1) / T;          // 49
    __shared__ int part[T];
    int t = threadIdx.x;
    int base = t * C;
    int local = 0;
#pragma unroll 4
    for (int j = 0; j < C; j++) {
        int idx = base + j;
        if (idx < n) local += g_deg[idx];
    }
    part[t] = local;
    __syncthreads();
    for (int off = 1; off < T; off <<= 1) {
        int v = (t >= off) ? part[t - off] : 0;
        __syncthreads();
        part[t] += v;
        __syncthreads();
    }
    int run = (t == 0) ? 0 : part[t - 1];
    for (int j = 0; j < C; j++) {
        int idx = base + j;
        if (idx < n) {
            g_rowptr[idx] = run;
            g_cursor[idx] = run;
            int d = g_deg[idx];
            run += d;
            g_dinv[idx] = rsqrtf((float)(d + 1));   // +1 self loop
        }
    }
    if (t == T - 1) g_rowptr[n] = EE;
}

// ---------------- CSR fill ----------------
__global__ void k_csr_fill(const int* __restrict__ row, const int* __restrict__ col, int e) {
    int i = blockIdx.x * blockDim.x + threadIdx.x;
    if (i >= e) return;
    int r = row[i];
    int p = atomicAdd(&g_cursor[r], 1);
    g_ecol[p] = col[i];
}

// ---------------- 128x(TN) register-blocked, double-buffered SGEMM ----------------
// 256 threads, micro-tile 8 x (TN/16), BK=8, 2-stage smem pipeline.
template <int TN, bool V4STORE>
__global__ void __launch_bounds__(256, 2) k_gemm128(const float* __restrict__ A,
                                                    const float* __restrict__ B,
                                                    float* __restrict__ C,
                                                    const float* __restrict__ bias,
                                                    int M, int K, int Nc) {
    constexpr int CN = TN / 16;               // cols per thread (8 or 4)
    __shared__ float As[2][8][128];           // [buf][k][m]
    __shared__ float Bs[2][8][TN];            // [buf][k][n]

    const int bm = blockIdx.y * 128;
    const int bn = blockIdx.x * TN;
    const int tid = threadIdx.x;
    const int tx = tid & 15;                  // n-dir
    const int ty = tid >> 4;                  // m-dir

    const int a_row = tid >> 1;               // 0..127
    const int a_kq  = (tid & 1) * 4;          // 0 or 4
    const bool bact = (TN == 128) || (tid < 128);
    const int b_krow = (TN == 128) ? (tid >> 5) : (tid >> 4);
    const int b_c4   = (TN == 128) ? ((tid & 31) * 4) : ((tid & 15) * 4);

    float acc[8][CN];
#pragma unroll
    for (int i = 0; i < 8; i++)
#pragma unroll
        for (int j = 0; j < CN; j++) acc[i][j] = 0.f;

    const int m_frag = ty * 8;
    const int n_frag = tx * CN;
    const int gm_a = bm + a_row;

    float4 ra, rb;
    // prologue: load tile 0 into regs, stage to buf 0
    {
        ra = make_float4(0.f, 0.f, 0.f, 0.f);
        if (gm_a < M) ra = *(const float4*)(A + (size_t)gm_a * K + 0 + a_kq);
        if (bact)     rb = *(const float4*)(B + (size_t)(0 + b_krow) * Nc + bn + b_c4);
        As[0][a_kq + 0][a_row] = ra.x;
        As[0][a_kq + 1][a_row] = ra.y;
        As[0][a_kq + 2][a_row] = ra.z;
        As[0][a_kq + 3][a_row] = ra.w;
        if (bact) *(float4*)(&Bs[0][b_krow][b_c4]) = rb;
    }
    __syncthreads();

    int buf = 0;
    for (int k0 = 0; k0 < K; k0 += 8) {
        // prefetch next tile into regs (overlaps with compute below)
        const bool more = (k0 + 8) < K;
        if (more) {
            ra = make_float4(0.f, 0.f, 0.f, 0.f);
            if (gm_a < M) ra = *(const float4*)(A + (size_t)gm_a * K + (k0 + 8) + a_kq);
            if (bact)     rb = *(const float4*)(B + (size_t)(k0 + 8 + b_krow) * Nc + bn + b_c4);
        }
        // compute current tile
#pragma unroll
        for (int k = 0; k < 8; k++) {
            float a[8], b[CN];
            *(float4*)(a)     = *(const float4*)(&As[buf][k][m_frag]);
            *(float4*)(a + 4) = *(const float4*)(&As[buf][k][m_frag + 4]);
            *(float4*)(b)     = *(const float4*)(&Bs[buf][k][n_frag]);
            if (CN == 8) *(float4*)(b + 4) = *(const float4*)(&Bs[buf][k][n_frag + 4]);
#pragma unroll
            for (int i = 0; i < 8; i++)
#pragma unroll
                for (int j = 0; j < CN; j++) acc[i][j] = fmaf(a[i], b[j], acc[i][j]);
        }
        if (more) {
            int nb2 = buf ^ 1;
            As[nb2][a_kq + 0][a_row] = ra.x;
            As[nb2][a_kq + 1][a_row] = ra.y;
            As[nb2][a_kq + 2][a_row] = ra.z;
            As[nb2][a_kq + 3][a_row] = ra.w;
            if (bact) *(float4*)(&Bs[nb2][b_krow][b_c4]) = rb;
            __syncthreads();
            buf = nb2;
        }
    }

#pragma unroll
    for (int i = 0; i < 8; i++) {
        int gm = bm + m_frag + i;
        if (gm >= M) continue;
        float* crow = C + (size_t)gm * Nc + bn + n_frag;
        if (V4STORE) {
#pragma unroll
            for (int j = 0; j < CN; j += 4) {
                float4 v;
                v.x = acc[i][j + 0]; v.y = acc[i][j + 1];
                v.z = acc[i][j + 2]; v.w = acc[i][j + 3];
                if (bias) {
                    v.x += bias[bn + n_frag + j + 0];
                    v.y += bias[bn + n_frag + j + 1];
                    v.z += bias[bn + n_frag + j + 2];
                    v.w += bias[bn + n_frag + j + 3];
                }
                *(float4*)(crow + j) = v;
            }
        } else {
#pragma unroll
            for (int j = 0; j < CN; j++) {
                float v = acc[i][j];
                if (bias) v += bias[bn + n_frag + j];
                crow[j] = v;
            }
        }
    }
}

// ---------------- fused gather conv, float4, 4 edge-groups x 64 feature-quads ----------------
// out_row = dinv[r]*( sum_edges dinv[c]*h[c] + dinv[r]*h[r] ) + b
// MODE 0: relu -> out ; MODE 1: double-l2norm -> out
template <int MODE>
__global__ void __launch_bounds__(256) k_gather(const float* __restrict__ h,
                                                const float* __restrict__ bias,
                                                float* __restrict__ out) {
    const int r   = blockIdx.x;
    const int tid = threadIdx.x;
    const int grp = tid >> 6;                 // 0..3 edge group
    const int q   = tid & 63;                 // feature quad (4q..4q+3)
    const int s = g_rowptr[r];
    const int e = g_rowptr[r + 1];

    __shared__ int   sc[256];
    __shared__ float sd[256];
    __shared__ float4 red[4][64];             // per-group partial sums

    float4 acc = make_float4(0.f, 0.f, 0.f, 0.f);
    for (int base = s; base < e; base += 256) {
        int nb = min(256, e - base);
        if (tid < nb) {
            int c = g_ecol[base + tid];
            sc[tid] = c;
            sd[tid] = g_dinv[c];
        }
        __syncthreads();
        for (int j = grp; j < nb; j += 4) {
            int c = sc[j];
            float d = sd[j];
            float4 v = __ldg((const float4*)(h + (size_t)c * HID) + q);
            acc.x = fmaf(d, v.x, acc.x);
            acc.y = fmaf(d, v.y, acc.y);
            acc.z = fmaf(d, v.z, acc.z);
            acc.w = fmaf(d, v.w, acc.w);
        }
        __syncthreads();
    }
    red[grp][q] = acc;
    __syncthreads();

    // every thread reconstructs the combined value for its quad (uniform control flow)
    float4 t0 = red[0][q], t1 = red[1][q], t2 = red[2][q], t3 = red[3][q];
    float4 sum;
    sum.x = (t0.x + t1.x) + (t2.x + t3.x);
    sum.y = (t0.y + t1.y) + (t2.y + t3.y);
    sum.z = (t0.z + t1.z) + (t2.z + t3.z);
    sum.w = (t0.w + t1.w) + (t2.w + t3.w);

    const float di = g_dinv[r];
    float4 hv = __ldg((const float4*)(h + (size_t)r * HID) + q);
    float4 bv = __ldg((const float4*)bias + q);
    float4 v;
    v.x = di * (sum.x + di * hv.x) + bv.x;
    v.y = di * (sum.y + di * hv.y) + bv.y;
    v.z = di * (sum.z + di * hv.z) + bv.z;
    v.w = di * (sum.w + di * hv.w) + bv.w;

    if (MODE == 0) {
        if (grp == 0) {
            float4 o;
            o.x = fmaxf(v.x, 0.f); o.y = fmaxf(v.y, 0.f);
            o.z = fmaxf(v.z, 0.f); o.w = fmaxf(v.w, 0.f);
            *((float4*)(out + (size_t)r * HID) + q) = o;
        }
    } else {
        // all 256 threads hold v (4x redundant across groups) -> block sumsq / 4
        float sq = v.x * v.x + v.y * v.y + v.z * v.z + v.w * v.w;
#pragma unroll
        for (int o = 16; o; o >>= 1) sq += __shfl_xor_sync(0xffffffffu, sq, o);
        __shared__ float ws[8];
        __shared__ float total;
        int wid = tid >> 5;
        if ((tid & 31) == 0) ws[wid] = sq;
        __syncthreads();
        if (tid == 0) {
            float t = 0.f;
#pragma unroll
            for (int k = 0; k < 8; k++) t += ws[k];
            total = t * 0.25f;                 // each feature counted 4x
        }
        __syncthreads();
        float s1 = sqrtf(total);
        float d1 = fmaxf(s1, 1e-12f);
        float s2 = s1 / d1;
        float d2 = fmaxf(s2, 1e-12f);
        float inv = 1.f / (d1 * d2);
        if (grp == 0) {
            float4 o;
            o.x = v.x * inv; o.y = v.y * inv; o.z = v.z * inv; o.w = v.w * inv;
            *((float4*)(out + (size_t)r * HID) + q) = o;
        }
    }
}

// ---------------- loss ----------------
__device__ __forceinline__ float dot256(const float* __restrict__ a,
                                        const float* __restrict__ b, int lane) {
    const float4* a4 = (const float4*)a;
    const float4* b4 = (const float4*)b;
    float s = 0.f;
#pragma unroll
    for (int j = 0; j < 2; j++) {
        float4 x = a4[lane + 32 * j];
        float4 y = b4[lane + 32 * j];
        s += x.x * y.x + x.y * y.y + x.z * y.z + x.w * y.w;
    }
#pragma unroll
    for (int o = 16; o; o >>= 1) s += __shfl_xor_sync(0xffffffffu, s, o);
    return s;
}

__global__ void k_zero_loss() {
    g_pos_loss = 0.0; g_neg_loss = 0.0; g_pos_cnt = 0ull; g_neg_cnt = 0ull;
}

__global__ void k_loss(const int* __restrict__ e0, const int* __restrict__ e1,
                       const int* __restrict__ n0, const int* __restrict__ n1,
                       const float* __restrict__ feat, const float* __restrict__ rep,
                       const float* __restrict__ ls) {
    int gw = (blockIdx.x * blockDim.x + threadIdx.x) >> 5;
    int lane = threadIdx.x & 31;
    int wid = threadIdx.x >> 5;

    float pos_local = 0.f, neg_local = 0.f;
    int pc = 0, nc = 0;
    if (gw < EE) {
        int a = e0[gw], b = e1[gw];
        if (a < b) {
            float fsim = dot256(feat + (size_t)a * FEA, feat + (size_t)b * FEA, lane);
            float wv   = dot256(rep  + (size_t)a * HID, rep  + (size_t)b * HID, lane);
            float pos = fsim * THETA + fmaxf(wv, 0.f) * (1.0f - THETA);
            float t = pos - ls[gw];
            pos_local = t * t;
            pc = 1;
        }
    } else if (gw < 2 * EE) {
        int k = gw - EE;
        int a = n0[k], b = n1[k];
        if (a < b) {
            float wv = fmaxf(dot256(rep + (size_t)a * HID, rep + (size_t)b * HID, lane), 0.f);
            neg_local = wv * wv;
            nc = 1;
        }
    }

    __shared__ float sp[16], sn[16];
    __shared__ int   cp[16], cn[16];
    if (lane == 0) { sp[wid] = pos_local; sn[wid] = neg_local; cp[wid] = pc; cn[wid] = nc; }
    __syncthreads();
    if (threadIdx.x == 0) {
        double p = 0.0, q = 0.0; int c1 = 0, c2 = 0;
#pragma unroll
        for (int k = 0; k < 16; k++) { p += sp[k]; q += sn[k]; c1 += cp[k]; c2 += cn[k]; }
        if (p != 0.0) atomicAdd(&g_pos_loss, p);
        if (q != 0.0) atomicAdd(&g_neg_loss, q);
        if (c1) atomicAdd(&g_pos_cnt, (unsigned long long)c1);
        if (c2) atomicAdd(&g_neg_cnt, (unsigned long long)c2);
    }
}

__global__ void k_finish_loss(float* __restrict__ out_scalar) {
    double tot = g_pos_loss + g_neg_loss;
    double denom = (double)(g_pos_cnt + g_neg_cnt);
    out_scalar[0] = (float)(tot * (double)NN / denom);
}

// ---------------- launch ----------------
extern "C" void kernel_launch(void* const* d_in, const int* in_sizes, int n_in,
                              void* d_out, int out_size) {
    const int*   edge_index = (const int*)d_in[0];       // [2,E]
    const float* features   = (const float*)d_in[1];     // [N,256]
    const float* label_sm   = (const float*)d_in[2];     // [E]
    const int*   neg_edge   = (const int*)d_in[3];       // [2,E]
    const float* W1 = (const float*)d_in[4];
    const float* b1 = (const float*)d_in[5];
    const float* W2 = (const float*)d_in[6];
    const float* b2 = (const float*)d_in[7];
    const float* Wy = (const float*)d_in[8];
    const float* by = (const float*)d_in[9];

    const int* e0 = edge_index;
    const int* e1 = edge_index + EE;
    const int* n0 = neg_edge;
    const int* n1 = neg_edge + EE;

    float* rep_out  = (float*)d_out;                           // [N,256]
    float* loss_out = (float*)d_out + (size_t)NN * HID;        // [1]
    float* y_out    = loss_out + 1;                            // [N,64] -- only 4B aligned!

    void *p_deg, *ph, *px;
    cudaGetSymbolAddress(&p_deg, g_deg);
    cudaGetSymbolAddress(&ph, g_h);
    cudaGetSymbolAddress(&px, g_x1);
    float* h  = (float*)ph;
    float* x1 = (float*)px;

    // 1. CSR build (degree -> scan -> fill). Also computes dinv.
    cudaMemsetAsync(p_deg, 0, NN * sizeof(int));
    k_deg_count<<<(EE + 255) / 256, 256>>>(e0, EE);
    k_scan<<<1, 1024>>>(NN);
    k_csr_fill<<<(EE + 255) / 256, 256>>>(e0, e1, EE);

    // 2. conv1: h = features @ W1 ; fused gather+relu -> x1
    {
        dim3 grid(HID / 128, (NN + 127) / 128), block(256);
        k_gemm128<128, true><<<grid, block>>>(features, W1, h, nullptr, NN, FEA, HID);
    }
    k_gather<0><<<NN, 256>>>(h, b1, x1);

    // 3. conv2: h = x1 @ W2 ; fused gather + double l2norm -> rep
    {
        dim3 grid(HID / 128, (NN + 127) / 128), block(256);
        k_gemm128<128, true><<<grid, block>>>(x1, W2, h, nullptr, NN, HID, HID);
    }
    k_gather<1><<<NN, 256>>>(h, b2, rep_out);

    // 4. y = rep @ Wy + by  (y_out is 4B-aligned only -> scalar stores)
    {
        dim3 grid(CLS / 64, (NN + 127) / 128), block(256);
        k_gemm128<64, false><<<grid, block>>>(rep_out, Wy, y_out, by, NN, HID, CLS);
    }

    // 5. loss
    k_zero_loss<<<1, 1>>>();
    {
        long long warps = 2LL * EE;
        int blocks = (int)((warps * 32 + 511) / 512);
        k_loss<<<blocks, 512>>>(e0, e1, n0, n1, features, rep_out, label_sm);
    }
    k_finish_loss<<<1, 1>>>(loss_out);
}

// round 8
// speedup vs baseline: 1.2549x; 1.2549x over previous
#include <cuda_runtime.h>
#include <cuda_bf16.h>
#include <math.h>

// Problem constants (static per reference).
#define NN   50000
#define EE   800000
#define FEA  256
#define HID  256
#define CLS  64
#define THETA 0.5f

// ---------------- device scratch (no allocs allowed) ----------------
__device__ int    g_deg[NN];
__device__ float  g_dinv[NN];
__device__ int    g_rowptr[NN + 1];
__device__ int    g_cursor[NN];
__device__ int    g_ecol[EE];                // CSR column indices
__device__ float  g_h  [(size_t)NN * HID];   // h = x @ W (current layer)
__device__ float  g_x1 [(size_t)NN * HID];   // relu'd conv1 output
__device__ double g_pos_loss;
__device__ double g_neg_loss;
__device__ unsigned long long g_pos_cnt;
__device__ unsigned long long g_neg_cnt;

// ---------------- degree ----------------
__global__ void k_deg_count(const int* __restrict__ row, int e) {
    int i = blockIdx.x * blockDim.x + threadIdx.x;
    if (i < e) atomicAdd(&g_deg[row[i]], 1);
}

// ---------------- single-block scan over g_deg -> g_rowptr, g_cursor, g_dinv ----------------
__global__ void k_scan(int n) {
    const int T = 1024;
    const int C = (NN + T - 1) / T;
    __shared__ int part[T];
    int t = threadIdx.x;
    int base = t * C;
    int local = 0;
#pragma unroll 4
    for (int j = 0; j < C; j++) {
        int idx = base + j;
        if (idx < n) local += g_deg[idx];
    }
    part[t] = local;
    __syncthreads();
    for (int off = 1; off < T; off <<= 1) {
        int v = (t >= off) ? part[t - off] : 0;
        __syncthreads();
        part[t] += v;
        __syncthreads();
    }
    int run = (t == 0) ? 0 : part[t - 1];
    for (int j = 0; j < C; j++) {
        int idx = base + j;
        if (idx < n) {
            g_rowptr[idx] = run;
            g_cursor[idx] = run;
            int d = g_deg[idx];
            run += d;
            g_dinv[idx] = rsqrtf((float)(d + 1));   // +1 self loop
        }
    }
    if (t == T - 1) g_rowptr[n] = EE;
}

// ---------------- CSR fill ----------------
__global__ void k_csr_fill(const int* __restrict__ row, const int* __restrict__ col, int e) {
    int i = blockIdx.x * blockDim.x + threadIdx.x;
    if (i >= e) return;
    int r = row[i];
    int p = atomicAdd(&g_cursor[r], 1);
    g_ecol[p] = col[i];
}

// ---------------- tf32 tensor-core GEMM: C[M,Nc] = A[M,K] @ B[K,Nc] ----------------
// BM=128, BN=128, BK=32. 8 warps (4m x 2n), warp tile 32x64, mma.m16n8k8.tf32.
__device__ __forceinline__ unsigned f2tf32(float f) {
    unsigned r;
    asm("cvt.rna.tf32.f32 %0, %1;" : "=r"(r) : "f"(f));
    return r;
}

__global__ void __launch_bounds__(256, 2) k_gemm_tf32(const float* __restrict__ A,
                                                      const float* __restrict__ B,
                                                      float* __restrict__ C,
                                                      int M, int K, int Nc) {
    __shared__ float As[128 * 36];            // [m][k] padded stride 36
    __shared__ float Bs[32 * 132];            // [k][n] padded stride 132

    const int tid  = threadIdx.x;
    const int wid  = tid >> 5;
    const int lane = tid & 31;
    const int g    = lane >> 2;               // 0..7
    const int tg   = lane & 3;                // 0..3
    const int warp_m = wid & 3;               // 0..3
    const int warp_n = wid >> 2;              // 0..1
    const int m_base = warp_m * 32;
    const int n_base = warp_n * 64;
    const int bm = blockIdx.y * 128;
    const int bn = blockIdx.x * 128;

    float c[2][8][4];
#pragma unroll
    for (int mi = 0; mi < 2; mi++)
#pragma unroll
        for (int ni = 0; ni < 8; ni++)
#pragma unroll
            for (int q = 0; q < 4; q++) c[mi][ni][q] = 0.f;

    for (int k0 = 0; k0 < K; k0 += 32) {
        // stage A tile (128 x 32), converted to tf32 bit patterns
#pragma unroll
        for (int i = 0; i < 4; i++) {
            int idx = tid + i * 256;          // 0..1023
            int row = idx >> 3, kq = (idx & 7) * 4;
            int gm = bm + row;
            float4 v = make_float4(0.f, 0.f, 0.f, 0.f);
            if (gm < M) v = *(const float4*)(A + (size_t)gm * K + k0 + kq);
            float* dst = As + row * 36 + kq;
            dst[0] = __uint_as_float(f2tf32(v.x));
            dst[1] = __uint_as_float(f2tf32(v.y));
            dst[2] = __uint_as_float(f2tf32(v.z));
            dst[3] = __uint_as_float(f2tf32(v.w));
        }
        // stage B tile (32 x 128)
#pragma unroll
        for (int i = 0; i < 4; i++) {
            int idx = tid + i * 256;
            int row = idx >> 5, c4 = (idx & 31) * 4;
            float4 v = *(const float4*)(B + (size_t)(k0 + row) * Nc + bn + c4);
            float* dst = Bs + row * 132 + c4;
            dst[0] = __uint_as_float(f2tf32(v.x));
            dst[1] = __uint_as_float(f2tf32(v.y));
            dst[2] = __uint_as_float(f2tf32(v.z));
            dst[3] = __uint_as_float(f2tf32(v.w));
        }
        __syncthreads();

#pragma unroll
        for (int kk = 0; kk < 4; kk++) {
            unsigned a[2][4], b[8][2];
#pragma unroll
            for (int mi = 0; mi < 2; mi++) {
                int r0 = m_base + mi * 16 + g;
                a[mi][0] = __float_as_uint(As[r0 * 36 + kk * 8 + tg]);
                a[mi][1] = __float_as_uint(As[(r0 + 8) * 36 + kk * 8 + tg]);
                a[mi][2] = __float_as_uint(As[r0 * 36 + kk * 8 + tg + 4]);
                a[mi][3] = __float_as_uint(As[(r0 + 8) * 36 + kk * 8 + tg + 4]);
            }
#pragma unroll
            for (int ni = 0; ni < 8; ni++) {
                int col = n_base + ni * 8 + g;
                b[ni][0] = __float_as_uint(Bs[(kk * 8 + tg) * 132 + col]);
                b[ni][1] = __float_as_uint(Bs[(kk * 8 + tg + 4) * 132 + col]);
            }
#pragma unroll
            for (int mi = 0; mi < 2; mi++)
#pragma unroll
                for (int ni = 0; ni < 8; ni++) {
                    asm volatile(
                        "mma.sync.aligned.m16n8k8.row.col.f32.tf32.tf32.f32 "
                        "{%0,%1,%2,%3}, {%4,%5,%6,%7}, {%8,%9}, {%0,%1,%2,%3};"
                        : "+f"(c[mi][ni][0]), "+f"(c[mi][ni][1]),
                          "+f"(c[mi][ni][2]), "+f"(c[mi][ni][3])
                        : "r"(a[mi][0]), "r"(a[mi][1]), "r"(a[mi][2]), "r"(a[mi][3]),
                          "r"(b[ni][0]), "r"(b[ni][1]));
                }
        }
        __syncthreads();
    }

    // epilogue: c0,c1 -> (row, 2tg), (row, 2tg+1); c2,c3 -> row+8
#pragma unroll
    for (int mi = 0; mi < 2; mi++) {
        int row0 = bm + m_base + mi * 16 + g;
        int row1 = row0 + 8;
#pragma unroll
        for (int ni = 0; ni < 8; ni++) {
            int col = bn + n_base + ni * 8 + 2 * tg;
            if (row0 < M) {
                float2 v0 = make_float2(c[mi][ni][0], c[mi][ni][1]);
                *(float2*)(C + (size_t)row0 * Nc + col) = v0;
            }
            if (row1 < M) {
                float2 v1 = make_float2(c[mi][ni][2], c[mi][ni][3]);
                *(float2*)(C + (size_t)row1 * Nc + col) = v1;
            }
        }
    }
}

// ---------------- 128x(TN) register-blocked fp32 SGEMM (for Wy) ----------------
template <int TN, bool V4STORE>
__global__ void __launch_bounds__(256, 2) k_gemm128(const float* __restrict__ A,
                                                    const float* __restrict__ B,
                                                    float* __restrict__ C,
                                                    const float* __restrict__ bias,
                                                    int M, int K, int Nc) {
    constexpr int CN = TN / 16;
    __shared__ float As[8][128];
    __shared__ float Bs[8][TN];

    const int bm = blockIdx.y * 128;
    const int bn = blockIdx.x * TN;
    const int tid = threadIdx.x;
    const int tx = tid & 15;
    const int ty = tid >> 4;

    const int a_row = tid >> 1;
    const int a_kq  = (tid & 1) * 4;
    const bool bact = (TN == 128) || (tid < 128);
    const int b_krow = (TN == 128) ? (tid >> 5) : (tid >> 4);
    const int b_c4   = (TN == 128) ? ((tid & 31) * 4) : ((tid & 15) * 4);

    float acc[8][CN];
#pragma unroll
    for (int i = 0; i < 8; i++)
#pragma unroll
        for (int j = 0; j < CN; j++) acc[i][j] = 0.f;

    const int m_frag = ty * 8;
    const int n_frag = tx * CN;
    const int gm_a = bm + a_row;

    for (int k0 = 0; k0 < K; k0 += 8) {
        {
            float4 v = make_float4(0.f, 0.f, 0.f, 0.f);
            if (gm_a < M) v = *(const float4*)(A + (size_t)gm_a * K + k0 + a_kq);
            As[a_kq + 0][a_row] = v.x;
            As[a_kq + 1][a_row] = v.y;
            As[a_kq + 2][a_row] = v.z;
            As[a_kq + 3][a_row] = v.w;
        }
        if (bact) {
            float4 v = *(const float4*)(B + (size_t)(k0 + b_krow) * Nc + bn + b_c4);
            *(float4*)(&Bs[b_krow][b_c4]) = v;
        }
        __syncthreads();
#pragma unroll
        for (int k = 0; k < 8; k++) {
            float a[8], b[CN];
            *(float4*)(a)     = *(const float4*)(&As[k][m_frag]);
            *(float4*)(a + 4) = *(const float4*)(&As[k][m_frag + 4]);
            *(float4*)(b)     = *(const float4*)(&Bs[k][n_frag]);
            if (CN == 8) *(float4*)(b + 4) = *(const float4*)(&Bs[k][n_frag + 4]);
#pragma unroll
            for (int i = 0; i < 8; i++)
#pragma unroll
                for (int j = 0; j < CN; j++) acc[i][j] = fmaf(a[i], b[j], acc[i][j]);
        }
        __syncthreads();
    }

#pragma unroll
    for (int i = 0; i < 8; i++) {
        int gm = bm + m_frag + i;
        if (gm >= M) continue;
        float* crow = C + (size_t)gm * Nc + bn + n_frag;
        if (V4STORE) {
#pragma unroll
            for (int j = 0; j < CN; j += 4) {
                float4 v;
                v.x = acc[i][j + 0]; v.y = acc[i][j + 1];
                v.z = acc[i][j + 2]; v.w = acc[i][j + 3];
                if (bias) {
                    v.x += bias[bn + n_frag + j + 0];
                    v.y += bias[bn + n_frag + j + 1];
                    v.z += bias[bn + n_frag + j + 2];
                    v.w += bias[bn + n_frag + j + 3];
                }
                *(float4*)(crow + j) = v;
            }
        } else {
#pragma unroll
            for (int j = 0; j < CN; j++) {
                float v = acc[i][j];
                if (bias) v += bias[bn + n_frag + j];
                crow[j] = v;
            }
        }
    }
}

// ---------------- fused gather conv, float4, 4 edge-groups x 64 feature-quads ----------------
template <int MODE>
__global__ void __launch_bounds__(256) k_gather(const float* __restrict__ h,
                                                const float* __restrict__ bias,
                                                float* __restrict__ out) {
    const int r   = blockIdx.x;
    const int tid = threadIdx.x;
    const int grp = tid >> 6;
    const int q   = tid & 63;
    const int s = g_rowptr[r];
    const int e = g_rowptr[r + 1];

    __shared__ int   sc[256];
    __shared__ float sd[256];
    __shared__ float4 red[4][64];

    float4 acc = make_float4(0.f, 0.f, 0.f, 0.f);
    for (int base = s; base < e; base += 256) {
        int nb = min(256, e - base);
        if (tid < nb) {
            int c = g_ecol[base + tid];
            sc[tid] = c;
            sd[tid] = g_dinv[c];
        }
        __syncthreads();
        for (int j = grp; j < nb; j += 4) {
            int c = sc[j];
            float d = sd[j];
            float4 v = __ldg((const float4*)(h + (size_t)c * HID) + q);
            acc.x = fmaf(d, v.x, acc.x);
            acc.y = fmaf(d, v.y, acc.y);
            acc.z = fmaf(d, v.z, acc.z);
            acc.w = fmaf(d, v.w, acc.w);
        }
        __syncthreads();
    }
    red[grp][q] = acc;
    __syncthreads();

    float4 t0 = red[0][q], t1 = red[1][q], t2 = red[2][q], t3 = red[3][q];
    float4 sum;
    sum.x = (t0.x + t1.x) + (t2.x + t3.x);
    sum.y = (t0.y + t1.y) + (t2.y + t3.y);
    sum.z = (t0.z + t1.z) + (t2.z + t3.z);
    sum.w = (t0.w + t1.w) + (t2.w + t3.w);

    const float di = g_dinv[r];
    float4 hv = __ldg((const float4*)(h + (size_t)r * HID) + q);
    float4 bv = __ldg((const float4*)bias + q);
    float4 v;
    v.x = di * (sum.x + di * hv.x) + bv.x;
    v.y = di * (sum.y + di * hv.y) + bv.y;
    v.z = di * (sum.z + di * hv.z) + bv.z;
    v.w = di * (sum.w + di * hv.w) + bv.w;

    if (MODE == 0) {
        if (grp == 0) {
            float4 o;
            o.x = fmaxf(v.x, 0.f); o.y = fmaxf(v.y, 0.f);
            o.z = fmaxf(v.z, 0.f); o.w = fmaxf(v.w, 0.f);
            *((float4*)(out + (size_t)r * HID) + q) = o;
        }
    } else {
        float sq = v.x * v.x + v.y * v.y + v.z * v.z + v.w * v.w;
#pragma unroll
        for (int o = 16; o; o >>= 1) sq += __shfl_xor_sync(0xffffffffu, sq, o);
        __shared__ float ws[8];
        __shared__ float total;
        int wid = tid >> 5;
        if ((tid & 31) == 0) ws[wid] = sq;
        __syncthreads();
        if (tid == 0) {
            float t = 0.f;
#pragma unroll
            for (int k = 0; k < 8; k++) t += ws[k];
            total = t * 0.25f;
        }
        __syncthreads();
        float s1 = sqrtf(total);
        float d1 = fmaxf(s1, 1e-12f);
        float s2 = s1 / d1;
        float d2 = fmaxf(s2, 1e-12f);
        float inv = 1.f / (d1 * d2);
        if (grp == 0) {
            float4 o;
            o.x = v.x * inv; o.y = v.y * inv; o.z = v.z * inv; o.w = v.w * inv;
            *((float4*)(out + (size_t)r * HID) + q) = o;
        }
    }
}

// ---------------- loss ----------------
__device__ __forceinline__ float dot256(const float* __restrict__ a,
                                        const float* __restrict__ b, int lane) {
    const float4* a4 = (const float4*)a;
    const float4* b4 = (const float4*)b;
    float s = 0.f;
#pragma unroll
    for (int j = 0; j < 2; j++) {
        float4 x = a4[lane + 32 * j];
        float4 y = b4[lane + 32 * j];
        s += x.x * y.x + x.y * y.y + x.z * y.z + x.w * y.w;
    }
#pragma unroll
    for (int o = 16; o; o >>= 1) s += __shfl_xor_sync(0xffffffffu, s, o);
    return s;
}

__global__ void k_zero_loss() {
    g_pos_loss = 0.0; g_neg_loss = 0.0; g_pos_cnt = 0ull; g_neg_cnt = 0ull;
}

__global__ void k_loss(const int* __restrict__ e0, const int* __restrict__ e1,
                       const int* __restrict__ n0, const int* __restrict__ n1,
                       const float* __restrict__ feat, const float* __restrict__ rep,
                       const float* __restrict__ ls) {
    int gw = (blockIdx.x * blockDim.x + threadIdx.x) >> 5;
    int lane = threadIdx.x & 31;
    int wid = threadIdx.x >> 5;

    float pos_local = 0.f, neg_local = 0.f;
    int pc = 0, nc = 0;
    if (gw < EE) {
        int a = e0[gw], b = e1[gw];
        if (a < b) {
            float fsim = dot256(feat + (size_t)a * FEA, feat + (size_t)b * FEA, lane);
            float wv   = dot256(rep  + (size_t)a * HID, rep  + (size_t)b * HID, lane);
            float pos = fsim * THETA + fmaxf(wv, 0.f) * (1.0f - THETA);
            float t = pos - ls[gw];
            pos_local = t * t;
            pc = 1;
        }
    } else if (gw < 2 * EE) {
        int k = gw - EE;
        int a = n0[k], b = n1[k];
        if (a < b) {
            float wv = fmaxf(dot256(rep + (size_t)a * HID, rep + (size_t)b * HID, lane), 0.f);
            neg_local = wv * wv;
            nc = 1;
        }
    }

    __shared__ float sp[16], sn[16];
    __shared__ int   cp[16], cn[16];
    if (lane == 0) { sp[wid] = pos_local; sn[wid] = neg_local; cp[wid] = pc; cn[wid] = nc; }
    __syncthreads();
    if (threadIdx.x == 0) {
        double p = 0.0, q = 0.0; int c1 = 0, c2 = 0;
#pragma unroll
        for (int k = 0; k < 16; k++) { p += sp[k]; q += sn[k]; c1 += cp[k]; c2 += cn[k]; }
        if (p != 0.0) atomicAdd(&g_pos_loss, p);
        if (q != 0.0) atomicAdd(&g_neg_loss, q);
        if (c1) atomicAdd(&g_pos_cnt, (unsigned long long)c1);
        if (c2) atomicAdd(&g_neg_cnt, (unsigned long long)c2);
    }
}

__global__ void k_finish_loss(float* __restrict__ out_scalar) {
    double tot = g_pos_loss + g_neg_loss;
    double denom = (double)(g_pos_cnt + g_neg_cnt);
    out_scalar[0] = (float)(tot * (double)NN / denom);
}

// ---------------- launch ----------------
extern "C" void kernel_launch(void* const* d_in, const int* in_sizes, int n_in,
                              void* d_out, int out_size) {
    const int*   edge_index = (const int*)d_in[0];
    const float* features   = (const float*)d_in[1];
    const float* label_sm   = (const float*)d_in[2];
    const int*   neg_edge   = (const int*)d_in[3];
    const float* W1 = (const float*)d_in[4];
    const float* b1 = (const float*)d_in[5];
    const float* W2 = (const float*)d_in[6];
    const float* b2 = (const float*)d_in[7];
    const float* Wy = (const float*)d_in[8];
    const float* by = (const float*)d_in[9];

    const int* e0 = edge_index;
    const int* e1 = edge_index + EE;
    const int* n0 = neg_edge;
    const int* n1 = neg_edge + EE;

    float* rep_out  = (float*)d_out;                           // [N,256]
    float* loss_out = (float*)d_out + (size_t)NN * HID;        // [1]
    float* y_out    = loss_out + 1;                            // [N,64] 4B-aligned only

    void *p_deg, *ph, *px;
    cudaGetSymbolAddress(&p_deg, g_deg);
    cudaGetSymbolAddress(&ph, g_h);
    cudaGetSymbolAddress(&px, g_x1);
    float* h  = (float*)ph;
    float* x1 = (float*)px;

    // 1. CSR build
    cudaMemsetAsync(p_deg, 0, NN * sizeof(int));
    k_deg_count<<<(EE + 255) / 256, 256>>>(e0, EE);
    k_scan<<<1, 1024>>>(NN);
    k_csr_fill<<<(EE + 255) / 256, 256>>>(e0, e1, EE);

    // 2. conv1: h = features @ W1 (tf32 tensor core) ; gather+relu -> x1
    {
        dim3 grid(HID / 128, (NN + 127) / 128), block(256);
        k_gemm_tf32<<<grid, block>>>(features, W1, h, NN, FEA, HID);
    }
    k_gather<0><<<NN, 256>>>(h, b1, x1);

    // 3. conv2: h = x1 @ W2 (tf32) ; gather + double l2norm -> rep
    {
        dim3 grid(HID / 128, (NN + 127) / 128), block(256);
        k_gemm_tf32<<<grid, block>>>(x1, W2, h, NN, HID, HID);
    }
    k_gather<1><<<NN, 256>>>(h, b2, rep_out);

    // 4. y = rep @ Wy + by (fp32; scalar stores for 4B-aligned y_out)
    {
        dim3 grid(CLS / 64, (NN + 127) / 128), block(256);
        k_gemm128<64, false><<<grid, block>>>(rep_out, Wy, y_out, by, NN, HID, CLS);
    }

    // 5. loss
    k_zero_loss<<<1, 1>>>();
    {
        long long warps = 2LL * EE;
        int blocks = (int)((warps * 32 + 511) / 512);
        k_loss<<<blocks, 512>>>(e0, e1, n0, n1, features, rep_out, label_sm);
    }
    k_finish_loss<<<1, 1>>>(loss_out);
}

// round 9
// speedup vs baseline: 1.4578x; 1.1618x over previous
#include <cuda_runtime.h>
#include <cuda_bf16.h>
#include <math.h>

// Problem constants (static per reference).
#define NN   50000
#define EE   800000
#define FEA  256
#define HID  256
#define CLS  64
#define THETA 0.5f

// ---------------- device scratch (no allocs allowed) ----------------
__device__ int    g_deg[NN];
__device__ float  g_dinv[NN];
__device__ int    g_rowptr[NN + 1];
__device__ int    g_cursor[NN];
__device__ int    g_ecol[EE];                // CSR column indices
__device__ float  g_h  [(size_t)NN * HID];   // h = x @ W (current layer)
__device__ float  g_x1 [(size_t)NN * HID];   // relu'd conv1 output
__device__ int2   g_pose[EE];                // compacted pos pairs (a<b)
__device__ float  g_pls [EE];                // their label_smoothing
__device__ int2   g_nege[EE];                // compacted neg pairs (a<b)
__device__ int    g_npos, g_nneg;
__device__ double g_pos_loss;
__device__ double g_neg_loss;

// ---------------- degree ----------------
__global__ void k_deg_count(const int* __restrict__ row, int e) {
    int i = blockIdx.x * blockDim.x + threadIdx.x;
    if (i < e) atomicAdd(&g_deg[row[i]], 1);
}

// ---------------- single-block scan over g_deg -> g_rowptr, g_cursor, g_dinv ----------------
__global__ void k_scan(int n) {
    const int T = 1024;
    const int C = (NN + T - 1) / T;
    __shared__ int part[T];
    int t = threadIdx.x;
    int base = t * C;
    int local = 0;
#pragma unroll 4
    for (int j = 0; j < C; j++) {
        int idx = base + j;
        if (idx < n) local += g_deg[idx];
    }
    part[t] = local;
    __syncthreads();
    for (int off = 1; off < T; off <<= 1) {
        int v = (t >= off) ? part[t - off] : 0;
        __syncthreads();
        part[t] += v;
        __syncthreads();
    }
    int run = (t == 0) ? 0 : part[t - 1];
    for (int j = 0; j < C; j++) {
        int idx = base + j;
        if (idx < n) {
            g_rowptr[idx] = run;
            g_cursor[idx] = run;
            int d = g_deg[idx];
            run += d;
            g_dinv[idx] = rsqrtf((float)(d + 1));   // +1 self loop
        }
    }
    if (t == T - 1) g_rowptr[n] = EE;
}

// ---------------- CSR fill ----------------
__global__ void k_csr_fill(const int* __restrict__ row, const int* __restrict__ col, int e) {
    int i = blockIdx.x * blockDim.x + threadIdx.x;
    if (i >= e) return;
    int r = row[i];
    int p = atomicAdd(&g_cursor[r], 1);
    g_ecol[p] = col[i];
}

// ---------------- tf32 tensor-core GEMM: C[M,Nc] = A[M,K] @ B[K,Nc] (+bias) ----------------
// BM=128, BK=32, BN template. 8 warps (4m x 2n), warp tile 32 x (BN/2), mma.m16n8k8.
__device__ __forceinline__ unsigned f2tf32(float f) {
    unsigned r;
    asm("cvt.rna.tf32.f32 %0, %1;" : "=r"(r) : "f"(f));
    return r;
}

template <int BN, bool V4OUT>
__global__ void __launch_bounds__(256, 2) k_gemm_tf32(const float* __restrict__ A,
                                                      const float* __restrict__ B,
                                                      float* __restrict__ C,
                                                      const float* __restrict__ bias,
                                                      int M, int K, int Nc) {
    constexpr int NI = BN / 16;               // mma n-tiles per warp
    constexpr int BS = BN + 4;                // padded Bs stride
    __shared__ float As[128 * 36];            // [m][k] padded stride 36
    __shared__ float Bs[32 * BS];             // [k][n]

    const int tid  = threadIdx.x;
    const int wid  = tid >> 5;
    const int lane = tid & 31;
    const int g    = lane >> 2;               // 0..7
    const int tg   = lane & 3;                // 0..3
    const int warp_m = wid & 3;               // 0..3
    const int warp_n = wid >> 2;              // 0..1
    const int m_base = warp_m * 32;
    const int n_base = warp_n * (BN / 2);
    const int bm = blockIdx.y * 128;
    const int bn = blockIdx.x * BN;

    float c[2][NI][4];
#pragma unroll
    for (int mi = 0; mi < 2; mi++)
#pragma unroll
        for (int ni = 0; ni < NI; ni++)
#pragma unroll
            for (int q = 0; q < 4; q++) c[mi][ni][q] = 0.f;

    for (int k0 = 0; k0 < K; k0 += 32) {
        // stage A tile (128 x 32) -> tf32
#pragma unroll
        for (int i = 0; i < 4; i++) {
            int idx = tid + i * 256;          // 0..1023
            int row = idx >> 3, kq = (idx & 7) * 4;
            int gm = bm + row;
            float4 v = make_float4(0.f, 0.f, 0.f, 0.f);
            if (gm < M) v = *(const float4*)(A + (size_t)gm * K + k0 + kq);
            float* dst = As + row * 36 + kq;
            dst[0] = __uint_as_float(f2tf32(v.x));
            dst[1] = __uint_as_float(f2tf32(v.y));
            dst[2] = __uint_as_float(f2tf32(v.z));
            dst[3] = __uint_as_float(f2tf32(v.w));
        }
        // stage B tile (32 x BN) -> tf32
#pragma unroll
        for (int i = 0; i < (32 * BN / 4) / 256; i++) {
            int idx = tid + i * 256;
            int row = idx / (BN / 4), c4 = (idx % (BN / 4)) * 4;
            float4 v = *(const float4*)(B + (size_t)(k0 + row) * Nc + bn + c4);
            float* dst = Bs + row * BS + c4;
            dst[0] = __uint_as_float(f2tf32(v.x));
            dst[1] = __uint_as_float(f2tf32(v.y));
            dst[2] = __uint_as_float(f2tf32(v.z));
            dst[3] = __uint_as_float(f2tf32(v.w));
        }
        __syncthreads();

#pragma unroll
        for (int kk = 0; kk < 4; kk++) {
            unsigned a[2][4], b[NI][2];
#pragma unroll
            for (int mi = 0; mi < 2; mi++) {
                int r0 = m_base + mi * 16 + g;
                a[mi][0] = __float_as_uint(As[r0 * 36 + kk * 8 + tg]);
                a[mi][1] = __float_as_uint(As[(r0 + 8) * 36 + kk * 8 + tg]);
                a[mi][2] = __float_as_uint(As[r0 * 36 + kk * 8 + tg + 4]);
                a[mi][3] = __float_as_uint(As[(r0 + 8) * 36 + kk * 8 + tg + 4]);
            }
#pragma unroll
            for (int ni = 0; ni < NI; ni++) {
                int col = n_base + ni * 8 + g;
                b[ni][0] = __float_as_uint(Bs[(kk * 8 + tg) * BS + col]);
                b[ni][1] = __float_as_uint(Bs[(kk * 8 + tg + 4) * BS + col]);
            }
#pragma unroll
            for (int mi = 0; mi < 2; mi++)
#pragma unroll
                for (int ni = 0; ni < NI; ni++) {
                    asm volatile(
                        "mma.sync.aligned.m16n8k8.row.col.f32.tf32.tf32.f32 "
                        "{%0,%1,%2,%3}, {%4,%5,%6,%7}, {%8,%9}, {%0,%1,%2,%3};"
                        : "+f"(c[mi][ni][0]), "+f"(c[mi][ni][1]),
                          "+f"(c[mi][ni][2]), "+f"(c[mi][ni][3])
                        : "r"(a[mi][0]), "r"(a[mi][1]), "r"(a[mi][2]), "r"(a[mi][3]),
                          "r"(b[ni][0]), "r"(b[ni][1]));
                }
        }
        __syncthreads();
    }

    // epilogue: c0,c1 -> (row0, col), (row0, col+1); c2,c3 -> row0+8
#pragma unroll
    for (int mi = 0; mi < 2; mi++) {
        int row0 = bm + m_base + mi * 16 + g;
        int row1 = row0 + 8;
#pragma unroll
        for (int ni = 0; ni < NI; ni++) {
            int col = bn + n_base + ni * 8 + 2 * tg;
            float b0 = 0.f, b1 = 0.f;
            if (bias) { b0 = bias[col]; b1 = bias[col + 1]; }
            if (V4OUT) {
                if (row0 < M)
                    *(float2*)(C + (size_t)row0 * Nc + col) =
                        make_float2(c[mi][ni][0] + b0, c[mi][ni][1] + b1);
                if (row1 < M)
                    *(float2*)(C + (size_t)row1 * Nc + col) =
                        make_float2(c[mi][ni][2] + b0, c[mi][ni][3] + b1);
            } else {
                if (row0 < M) {
                    C[(size_t)row0 * Nc + col]     = c[mi][ni][0] + b0;
                    C[(size_t)row0 * Nc + col + 1] = c[mi][ni][1] + b1;
                }
                if (row1 < M) {
                    C[(size_t)row1 * Nc + col]     = c[mi][ni][2] + b0;
                    C[(size_t)row1 * Nc + col + 1] = c[mi][ni][3] + b1;
                }
            }
        }
    }
}

// ---------------- fused gather conv, float4, 4 edge-groups x 64 feature-quads ----------------
template <int MODE>
__global__ void __launch_bounds__(256) k_gather(const float* __restrict__ h,
                                                const float* __restrict__ bias,
                                                float* __restrict__ out) {
    const int r   = blockIdx.x;
    const int tid = threadIdx.x;
    const int grp = tid >> 6;
    const int q   = tid & 63;
    const int s = g_rowptr[r];
    const int e = g_rowptr[r + 1];

    __shared__ int   sc[256];
    __shared__ float sd[256];
    __shared__ float4 red[4][64];

    float4 acc = make_float4(0.f, 0.f, 0.f, 0.f);
    for (int base = s; base < e; base += 256) {
        int nb = min(256, e - base);
        if (tid < nb) {
            int c = g_ecol[base + tid];
            sc[tid] = c;
            sd[tid] = g_dinv[c];
        }
        __syncthreads();
        for (int j = grp; j < nb; j += 4) {
            int c = sc[j];
            float d = sd[j];
            float4 v = __ldg((const float4*)(h + (size_t)c * HID) + q);
            acc.x = fmaf(d, v.x, acc.x);
            acc.y = fmaf(d, v.y, acc.y);
            acc.z = fmaf(d, v.z, acc.z);
            acc.w = fmaf(d, v.w, acc.w);
        }
        __syncthreads();
    }
    red[grp][q] = acc;
    __syncthreads();

    float4 t0 = red[0][q], t1 = red[1][q], t2 = red[2][q], t3 = red[3][q];
    float4 sum;
    sum.x = (t0.x + t1.x) + (t2.x + t3.x);
    sum.y = (t0.y + t1.y) + (t2.y + t3.y);
    sum.z = (t0.z + t1.z) + (t2.z + t3.z);
    sum.w = (t0.w + t1.w) + (t2.w + t3.w);

    const float di = g_dinv[r];
    float4 hv = __ldg((const float4*)(h + (size_t)r * HID) + q);
    float4 bv = __ldg((const float4*)bias + q);
    float4 v;
    v.x = di * (sum.x + di * hv.x) + bv.x;
    v.y = di * (sum.y + di * hv.y) + bv.y;
    v.z = di * (sum.z + di * hv.z) + bv.z;
    v.w = di * (sum.w + di * hv.w) + bv.w;

    if (MODE == 0) {
        if (grp == 0) {
            float4 o;
            o.x = fmaxf(v.x, 0.f); o.y = fmaxf(v.y, 0.f);
            o.z = fmaxf(v.z, 0.f); o.w = fmaxf(v.w, 0.f);
            *((float4*)(out + (size_t)r * HID) + q) = o;
        }
    } else {
        float sq = v.x * v.x + v.y * v.y + v.z * v.z + v.w * v.w;
#pragma unroll
        for (int o = 16; o; o >>= 1) sq += __shfl_xor_sync(0xffffffffu, sq, o);
        __shared__ float ws[8];
        __shared__ float total;
        int wid = tid >> 5;
        if ((tid & 31) == 0) ws[wid] = sq;
        __syncthreads();
        if (tid == 0) {
            float t = 0.f;
#pragma unroll
            for (int k = 0; k < 8; k++) t += ws[k];
            total = t * 0.25f;
        }
        __syncthreads();
        float s1 = sqrtf(total);
        float d1 = fmaxf(s1, 1e-12f);
        float s2 = s1 / d1;
        float d2 = fmaxf(s2, 1e-12f);
        float inv = 1.f / (d1 * d2);
        if (grp == 0) {
            float4 o;
            o.x = v.x * inv; o.y = v.y * inv; o.z = v.z * inv; o.w = v.w * inv;
            *((float4*)(out + (size_t)r * HID) + q) = o;
        }
    }
}

// ---------------- loss: compaction + dense evaluation ----------------
__global__ void k_zero_loss() {
    g_pos_loss = 0.0; g_neg_loss = 0.0; g_npos = 0; g_nneg = 0;
}

// block-aggregated compaction of a<b pairs
__global__ void k_compact(const int* __restrict__ e0, const int* __restrict__ e1,
                          const int* __restrict__ n0, const int* __restrict__ n1,
                          const float* __restrict__ ls) {
    int i = blockIdx.x * blockDim.x + threadIdx.x;
    __shared__ int scp, scn, sbp, sbn;
    if (threadIdx.x == 0) { scp = 0; scn = 0; }
    __syncthreads();
    int a = 0, b = 0, na = 0, nb = 0;
    bool vp = false, vn = false;
    int lp = 0, ln = 0;
    float lsv = 0.f;
    if (i < EE) {
        a = e0[i]; b = e1[i]; vp = a < b;
        na = n0[i]; nb = n1[i]; vn = na < nb;
        if (vp) lsv = ls[i];
    }
    if (vp) lp = atomicAdd(&scp, 1);
    if (vn) ln = atomicAdd(&scn, 1);
    __syncthreads();
    if (threadIdx.x == 0) {
        sbp = atomicAdd(&g_npos, scp);
        sbn = atomicAdd(&g_nneg, scn);
    }
    __syncthreads();
    if (vp) { int p = sbp + lp; g_pose[p] = make_int2(a, b); g_pls[p] = lsv; }
    if (vn) { int p = sbn + ln; g_nege[p] = make_int2(na, nb); }
}

__device__ __forceinline__ float dot256(const float* __restrict__ a,
                                        const float* __restrict__ b, int lane) {
    const float4* a4 = (const float4*)a;
    const float4* b4 = (const float4*)b;
    float s = 0.f;
#pragma unroll
    for (int j = 0; j < 2; j++) {
        float4 x = a4[lane + 32 * j];
        float4 y = b4[lane + 32 * j];
        s += x.x * y.x + x.y * y.y + x.z * y.z + x.w * y.w;
    }
#pragma unroll
    for (int o = 16; o; o >>= 1) s += __shfl_xor_sync(0xffffffffu, s, o);
    return s;
}

// warps [0, EE): pos list; warps [EE, 2EE): neg list. Guarded by runtime counts.
__global__ void k_loss(const float* __restrict__ feat, const float* __restrict__ rep) {
    int gw = (blockIdx.x * blockDim.x + threadIdx.x) >> 5;
    int lane = threadIdx.x & 31;
    int wid = threadIdx.x >> 5;
    const int npos = g_npos;
    const int nneg = g_nneg;

    float pos_local = 0.f, neg_local = 0.f;
    if (gw < EE) {
        if (gw < npos) {
            int2 p = __ldg(&g_pose[gw]);
            float fsim = dot256(feat + (size_t)p.x * FEA, feat + (size_t)p.y * FEA, lane);
            float wv   = dot256(rep  + (size_t)p.x * HID, rep  + (size_t)p.y * HID, lane);
            float pos = fsim * THETA + fmaxf(wv, 0.f) * (1.0f - THETA);
            float t = pos - __ldg(&g_pls[gw]);
            pos_local = t * t;
        }
    } else {
        int k = gw - EE;
        if (k < nneg) {
            int2 p = __ldg(&g_nege[k]);
            float wv = fmaxf(dot256(rep + (size_t)p.x * HID, rep + (size_t)p.y * HID, lane), 0.f);
            neg_local = wv * wv;
        }
    }

    __shared__ float sp[16], sn[16];
    if (lane == 0) { sp[wid] = pos_local; sn[wid] = neg_local; }
    __syncthreads();
    if (threadIdx.x == 0) {
        double p = 0.0, q = 0.0;
#pragma unroll
        for (int k = 0; k < 16; k++) { p += sp[k]; q += sn[k]; }
        if (p != 0.0) atomicAdd(&g_pos_loss, p);
        if (q != 0.0) atomicAdd(&g_neg_loss, q);
    }
}

__global__ void k_finish_loss(float* __restrict__ out_scalar) {
    double tot = g_pos_loss + g_neg_loss;
    double denom = (double)(g_npos + g_nneg);
    out_scalar[0] = (float)(tot * (double)NN / denom);
}

// ---------------- launch ----------------
extern "C" void kernel_launch(void* const* d_in, const int* in_sizes, int n_in,
                              void* d_out, int out_size) {
    const int*   edge_index = (const int*)d_in[0];
    const float* features   = (const float*)d_in[1];
    const float* label_sm   = (const float*)d_in[2];
    const int*   neg_edge   = (const int*)d_in[3];
    const float* W1 = (const float*)d_in[4];
    const float* b1 = (const float*)d_in[5];
    const float* W2 = (const float*)d_in[6];
    const float* b2 = (const float*)d_in[7];
    const float* Wy = (const float*)d_in[8];
    const float* by = (const float*)d_in[9];

    const int* e0 = edge_index;
    const int* e1 = edge_index + EE;
    const int* n0 = neg_edge;
    const int* n1 = neg_edge + EE;

    float* rep_out  = (float*)d_out;                           // [N,256]
    float* loss_out = (float*)d_out + (size_t)NN * HID;        // [1]
    float* y_out    = loss_out + 1;                            // [N,64] 4B-aligned only

    void *p_deg, *ph, *px;
    cudaGetSymbolAddress(&p_deg, g_deg);
    cudaGetSymbolAddress(&ph, g_h);
    cudaGetSymbolAddress(&px, g_x1);
    float* h  = (float*)ph;
    float* x1 = (float*)px;

    // 1. CSR build + loss compaction bookkeeping
    cudaMemsetAsync(p_deg, 0, NN * sizeof(int));
    k_zero_loss<<<1, 1>>>();
    k_deg_count<<<(EE + 255) / 256, 256>>>(e0, EE);
    k_scan<<<1, 1024>>>(NN);
    k_csr_fill<<<(EE + 255) / 256, 256>>>(e0, e1, EE);
    k_compact<<<(EE + 255) / 256, 256>>>(e0, e1, n0, n1, label_sm);

    // 2. conv1: h = features @ W1 (tf32) ; gather+relu -> x1
    {
        dim3 grid(HID / 128, (NN + 127) / 128), block(256);
        k_gemm_tf32<128, true><<<grid, block>>>(features, W1, h, nullptr, NN, FEA, HID);
    }
    k_gather<0><<<NN, 256>>>(h, b1, x1);

    // 3. conv2: h = x1 @ W2 (tf32) ; gather + double l2norm -> rep
    {
        dim3 grid(HID / 128, (NN + 127) / 128), block(256);
        k_gemm_tf32<128, true><<<grid, block>>>(x1, W2, h, nullptr, NN, HID, HID);
    }
    k_gather<1><<<NN, 256>>>(h, b2, rep_out);

    // 4. y = rep @ Wy + by (tf32; scalar stores for 4B-aligned y_out)
    {
        dim3 grid(CLS / 64, (NN + 127) / 128), block(256);
        k_gemm_tf32<64, false><<<grid, block>>>(rep_out, Wy, y_out, by, NN, HID, CLS);
    }

    // 5. loss over compacted lists
    {
        long long warps = 2LL * EE;
        int blocks = (int)((warps * 32 + 511) / 512);
        k_loss<<<blocks, 512>>>(features, rep_out);
    }
    k_finish_loss<<<1, 1>>>(loss_out);
}

// round 11
// speedup vs baseline: 1.6016x; 1.0986x over previous
#include <cuda_runtime.h>
#include <cuda_bf16.h>
#include <math.h>

// Problem constants (static per reference).
#define NN   50000
#define EE   800000
#define FEA  256
#define HID  256
#define CLS  64
#define THETA 0.5f

// ---------------- device scratch (no allocs allowed) ----------------
__device__ int    g_deg[NN];
__device__ float  g_dinv[NN];
__device__ int    g_rowptr[NN + 1];
__device__ int    g_cursor[NN];
__device__ int    g_ecol[EE];                      // CSR column indices
__device__ float  g_h  [(size_t)NN * HID];         // h = x @ W (current layer)
__device__ float  g_x1 [(size_t)NN * HID];         // relu'd conv1 output
__device__ __nv_bfloat16 g_feat_bf[(size_t)NN * FEA];  // bf16 features (loss)
__device__ __nv_bfloat16 g_rep_bf [(size_t)NN * HID];  // bf16 rep (loss)
__device__ int2   g_pose[EE];                      // compacted pos pairs (a<b)
__device__ float  g_pls [EE];                      // their label_smoothing
__device__ int2   g_nege[EE];                      // compacted neg pairs (a<b)
__device__ int    g_npos, g_nneg;
__device__ double g_pos_loss;
__device__ double g_neg_loss;

// ---------------- zero counters ----------------
__global__ void k_zero_loss() {
    g_pos_loss = 0.0; g_neg_loss = 0.0; g_npos = 0; g_nneg = 0;
}

// ---------------- fused: degree count + a<b pair compaction ----------------
__global__ void k_deg_compact(const int* __restrict__ e0, const int* __restrict__ e1,
                              const int* __restrict__ n0, const int* __restrict__ n1,
                              const float* __restrict__ ls) {
    int i = blockIdx.x * blockDim.x + threadIdx.x;
    __shared__ int scp, scn, sbp, sbn;
    if (threadIdx.x == 0) { scp = 0; scn = 0; }
    __syncthreads();
    int a = 0, b = 0, na = 0, nb = 0;
    bool vp = false, vn = false;
    int lp = 0, ln = 0;
    float lsv = 0.f;
    if (i < EE) {
        a = e0[i]; b = e1[i]; vp = a < b;
        na = n0[i]; nb = n1[i]; vn = na < nb;
        if (vp) lsv = ls[i];
        atomicAdd(&g_deg[a], 1);                   // degree over rows (e0)
    }
    if (vp) lp = atomicAdd(&scp, 1);
    if (vn) ln = atomicAdd(&scn, 1);
    __syncthreads();
    if (threadIdx.x == 0) {
        sbp = atomicAdd(&g_npos, scp);
        sbn = atomicAdd(&g_nneg, scn);
    }
    __syncthreads();
    if (vp) { int p = sbp + lp; g_pose[p] = make_int2(a, b); g_pls[p] = lsv; }
    if (vn) { int p = sbn + ln; g_nege[p] = make_int2(na, nb); }
}

// ---------------- single-block scan over g_deg -> g_rowptr, g_cursor, g_dinv ----------------
__global__ void k_scan(int n) {
    const int T = 1024;
    const int C = (NN + T - 1) / T;
    __shared__ int part[T];
    int t = threadIdx.x;
    int base = t * C;
    int local = 0;
#pragma unroll 4
    for (int j = 0; j < C; j++) {
        int idx = base + j;
        if (idx < n) local += g_deg[idx];
    }
    part[t] = local;
    __syncthreads();
    for (int off = 1; off < T; off <<= 1) {
        int v = (t >= off) ? part[t - off] : 0;
        __syncthreads();
        part[t] += v;
        __syncthreads();
    }
    int run = (t == 0) ? 0 : part[t - 1];
    for (int j = 0; j < C; j++) {
        int idx = base + j;
        if (idx < n) {
            g_rowptr[idx] = run;
            g_cursor[idx] = run;
            int d = g_deg[idx];
            run += d;
            g_dinv[idx] = rsqrtf((float)(d + 1));   // +1 self loop
        }
    }
    if (t == T - 1) g_rowptr[n] = EE;
}

// ---------------- CSR fill ----------------
__global__ void k_csr_fill(const int* __restrict__ row, const int* __restrict__ col, int e) {
    int i = blockIdx.x * blockDim.x + threadIdx.x;
    if (i >= e) return;
    int r = row[i];
    int p = atomicAdd(&g_cursor[r], 1);
    g_ecol[p] = col[i];
}

// ---------------- fp32 -> bf16 conversion (vectorized) ----------------
__global__ void k_f2bf(const float* __restrict__ src, __nv_bfloat16* __restrict__ dst,
                       int n4) {
    int i = blockIdx.x * blockDim.x + threadIdx.x;
    if (i >= n4) return;
    float4 v = ((const float4*)src)[i];
    __nv_bfloat162 lo = __float22bfloat162_rn(make_float2(v.x, v.y));
    __nv_bfloat162 hi = __float22bfloat162_rn(make_float2(v.z, v.w));
    ((__nv_bfloat162*)dst)[2 * i]     = lo;
    ((__nv_bfloat162*)dst)[2 * i + 1] = hi;
}

// ---------------- tf32 tensor-core GEMM: C[M,Nc] = A[M,K] @ B[K,Nc] (+bias) ----------------
__device__ __forceinline__ unsigned f2tf32(float f) {
    unsigned r;
    asm("cvt.rna.tf32.f32 %0, %1;" : "=r"(r) : "f"(f));
    return r;
}

template <int BN, bool V4OUT>
__global__ void __launch_bounds__(256, 2) k_gemm_tf32(const float* __restrict__ A,
                                                      const float* __restrict__ B,
                                                      float* __restrict__ C,
                                                      const float* __restrict__ bias,
                                                      int M, int K, int Nc) {
    constexpr int NI = BN / 16;
    constexpr int BS = BN + 4;
    __shared__ float As[128 * 36];
    __shared__ float Bs[32 * BS];

    const int tid  = threadIdx.x;
    const int wid  = tid >> 5;
    const int lane = tid & 31;
    const int g    = lane >> 2;
    const int tg   = lane & 3;
    const int warp_m = wid & 3;
    const int warp_n = wid >> 2;
    const int m_base = warp_m * 32;
    const int n_base = warp_n * (BN / 2);
    const int bm = blockIdx.y * 128;
    const int bn = blockIdx.x * BN;

    float c[2][NI][4];
#pragma unroll
    for (int mi = 0; mi < 2; mi++)
#pragma unroll
        for (int ni = 0; ni < NI; ni++)
#pragma unroll
            for (int q = 0; q < 4; q++) c[mi][ni][q] = 0.f;

    for (int k0 = 0; k0 < K; k0 += 32) {
#pragma unroll
        for (int i = 0; i < 4; i++) {
            int idx = tid + i * 256;
            int row = idx >> 3, kq = (idx & 7) * 4;
            int gm = bm + row;
            float4 v = make_float4(0.f, 0.f, 0.f, 0.f);
            if (gm < M) v = *(const float4*)(A + (size_t)gm * K + k0 + kq);
            float* dst = As + row * 36 + kq;
            dst[0] = __uint_as_float(f2tf32(v.x));
            dst[1] = __uint_as_float(f2tf32(v.y));
            dst[2] = __uint_as_float(f2tf32(v.z));
            dst[3] = __uint_as_float(f2tf32(v.w));
        }
#pragma unroll
        for (int i = 0; i < (32 * BN / 4) / 256; i++) {
            int idx = tid + i * 256;
            int row = idx / (BN / 4), c4 = (idx % (BN / 4)) * 4;
            float4 v = *(const float4*)(B + (size_t)(k0 + row) * Nc + bn + c4);
            float* dst = Bs + row * BS + c4;
            dst[0] = __uint_as_float(f2tf32(v.x));
            dst[1] = __uint_as_float(f2tf32(v.y));
            dst[2] = __uint_as_float(f2tf32(v.z));
            dst[3] = __uint_as_float(f2tf32(v.w));
        }
        __syncthreads();

#pragma unroll
        for (int kk = 0; kk < 4; kk++) {
            unsigned a[2][4], b[NI][2];
#pragma unroll
            for (int mi = 0; mi < 2; mi++) {
                int r0 = m_base + mi * 16 + g;
                a[mi][0] = __float_as_uint(As[r0 * 36 + kk * 8 + tg]);
                a[mi][1] = __float_as_uint(As[(r0 + 8) * 36 + kk * 8 + tg]);
                a[mi][2] = __float_as_uint(As[r0 * 36 + kk * 8 + tg + 4]);
                a[mi][3] = __float_as_uint(As[(r0 + 8) * 36 + kk * 8 + tg + 4]);
            }
#pragma unroll
            for (int ni = 0; ni < NI; ni++) {
                int col = n_base + ni * 8 + g;
                b[ni][0] = __float_as_uint(Bs[(kk * 8 + tg) * BS + col]);
                b[ni][1] = __float_as_uint(Bs[(kk * 8 + tg + 4) * BS + col]);
            }
#pragma unroll
            for (int mi = 0; mi < 2; mi++)
#pragma unroll
                for (int ni = 0; ni < NI; ni++) {
                    asm volatile(
                        "mma.sync.aligned.m16n8k8.row.col.f32.tf32.tf32.f32 "
                        "{%0,%1,%2,%3}, {%4,%5,%6,%7}, {%8,%9}, {%0,%1,%2,%3};"
                        : "+f"(c[mi][ni][0]), "+f"(c[mi][ni][1]),
                          "+f"(c[mi][ni][2]), "+f"(c[mi][ni][3])
                        : "r"(a[mi][0]), "r"(a[mi][1]), "r"(a[mi][2]), "r"(a[mi][3]),
                          "r"(b[ni][0]), "r"(b[ni][1]));
                }
        }
        __syncthreads();
    }

#pragma unroll
    for (int mi = 0; mi < 2; mi++) {
        int row0 = bm + m_base + mi * 16 + g;
        int row1 = row0 + 8;
#pragma unroll
        for (int ni = 0; ni < NI; ni++) {
            int col = bn + n_base + ni * 8 + 2 * tg;
            float b0 = 0.f, b1 = 0.f;
            if (bias) { b0 = bias[col]; b1 = bias[col + 1]; }
            if (V4OUT) {
                if (row0 < M)
                    *(float2*)(C + (size_t)row0 * Nc + col) =
                        make_float2(c[mi][ni][0] + b0, c[mi][ni][1] + b1);
                if (row1 < M)
                    *(float2*)(C + (size_t)row1 * Nc + col) =
                        make_float2(c[mi][ni][2] + b0, c[mi][ni][3] + b1);
            } else {
                if (row0 < M) {
                    C[(size_t)row0 * Nc + col]     = c[mi][ni][0] + b0;
                    C[(size_t)row0 * Nc + col + 1] = c[mi][ni][1] + b1;
                }
                if (row1 < M) {
                    C[(size_t)row1 * Nc + col]     = c[mi][ni][2] + b0;
                    C[(size_t)row1 * Nc + col + 1] = c[mi][ni][3] + b1;
                }
            }
        }
    }
}

// ---------------- fused gather conv ----------------
// MODE 0: relu -> out ; MODE 1: double-l2norm -> out (fp32) + bf16 copy
template <int MODE>
__global__ void __launch_bounds__(256) k_gather(const float* __restrict__ h,
                                                const float* __restrict__ bias,
                                                float* __restrict__ out) {
    const int r   = blockIdx.x;
    const int tid = threadIdx.x;
    const int grp = tid >> 6;
    const int q   = tid & 63;
    const int s = g_rowptr[r];
    const int e = g_rowptr[r + 1];

    __shared__ int   sc[256];
    __shared__ float sd[256];
    __shared__ float4 red[4][64];

    float4 acc = make_float4(0.f, 0.f, 0.f, 0.f);
    for (int base = s; base < e; base += 256) {
        int nb = min(256, e - base);
        if (tid < nb) {
            int c = g_ecol[base + tid];
            sc[tid] = c;
            sd[tid] = g_dinv[c];
        }
        __syncthreads();
        for (int j = grp; j < nb; j += 4) {
            int c = sc[j];
            float d = sd[j];
            float4 v = __ldg((const float4*)(h + (size_t)c * HID) + q);
            acc.x = fmaf(d, v.x, acc.x);
            acc.y = fmaf(d, v.y, acc.y);
            acc.z = fmaf(d, v.z, acc.z);
            acc.w = fmaf(d, v.w, acc.w);
        }
        __syncthreads();
    }
    red[grp][q] = acc;
    __syncthreads();

    float4 t0 = red[0][q], t1 = red[1][q], t2 = red[2][q], t3 = red[3][q];
    float4 sum;
    sum.x = (t0.x + t1.x) + (t2.x + t3.x);
    sum.y = (t0.y + t1.y) + (t2.y + t3.y);
    sum.z = (t0.z + t1.z) + (t2.z + t3.z);
    sum.w = (t0.w + t1.w) + (t2.w + t3.w);

    const float di = g_dinv[r];
    float4 hv = __ldg((const float4*)(h + (size_t)r * HID) + q);
    float4 bv = __ldg((const float4*)bias + q);
    float4 v;
    v.x = di * (sum.x + di * hv.x) + bv.x;
    v.y = di * (sum.y + di * hv.y) + bv.y;
    v.z = di * (sum.z + di * hv.z) + bv.z;
    v.w = di * (sum.w + di * hv.w) + bv.w;

    if (MODE == 0) {
        if (grp == 0) {
            float4 o;
            o.x = fmaxf(v.x, 0.f); o.y = fmaxf(v.y, 0.f);
            o.z = fmaxf(v.z, 0.f); o.w = fmaxf(v.w, 0.f);
            *((float4*)(out + (size_t)r * HID) + q) = o;
        }
    } else {
        float sq = v.x * v.x + v.y * v.y + v.z * v.z + v.w * v.w;
#pragma unroll
        for (int o = 16; o; o >>= 1) sq += __shfl_xor_sync(0xffffffffu, sq, o);
        __shared__ float ws[8];
        __shared__ float total;
        int wid = tid >> 5;
        if ((tid & 31) == 0) ws[wid] = sq;
        __syncthreads();
        if (tid == 0) {
            float t = 0.f;
#pragma unroll
            for (int k = 0; k < 8; k++) t += ws[k];
            total = t * 0.25f;
        }
        __syncthreads();
        float s1 = sqrtf(total);
        float d1 = fmaxf(s1, 1e-12f);
        float s2 = s1 / d1;
        float d2 = fmaxf(s2, 1e-12f);
        float inv = 1.f / (d1 * d2);
        if (grp == 0) {
            float4 o;
            o.x = v.x * inv; o.y = v.y * inv; o.z = v.z * inv; o.w = v.w * inv;
            *((float4*)(out + (size_t)r * HID) + q) = o;
            // bf16 copy for the loss kernel
            __nv_bfloat162 lo = __float22bfloat162_rn(make_float2(o.x, o.y));
            __nv_bfloat162 hi = __float22bfloat162_rn(make_float2(o.z, o.w));
            __nv_bfloat162* dst = (__nv_bfloat162*)(g_rep_bf + (size_t)r * HID) + 2 * q;
            dst[0] = lo;
            dst[1] = hi;
        }
    }
}

// ---------------- loss over compacted lists, bf16 operands ----------------
__device__ __forceinline__ float dotbf(const __nv_bfloat16* __restrict__ a,
                                       const __nv_bfloat16* __restrict__ b, int lane) {
    uint4 x = __ldg((const uint4*)a + lane);
    uint4 y = __ldg((const uint4*)b + lane);
    float s = 0.f;
    const unsigned* xs = (const unsigned*)&x;
    const unsigned* ys = (const unsigned*)&y;
#pragma unroll
    for (int j = 0; j < 4; j++) {
        float2 fx = __bfloat1622float2(*(const __nv_bfloat162*)&xs[j]);
        float2 fy = __bfloat1622float2(*(const __nv_bfloat162*)&ys[j]);
        s = fmaf(fx.x, fy.x, s);
        s = fmaf(fx.y, fy.y, s);
    }
#pragma unroll
    for (int o = 16; o; o >>= 1) s += __shfl_xor_sync(0xffffffffu, s, o);
    return s;
}

__global__ void k_loss(void) {
    int gw = (blockIdx.x * blockDim.x + threadIdx.x) >> 5;
    int lane = threadIdx.x & 31;
    int wid = threadIdx.x >> 5;
    const int npos = g_npos;
    const int nneg = g_nneg;

    float pos_local = 0.f, neg_local = 0.f;
    if (gw < EE) {
        if (gw < npos) {
            int2 p = __ldg(&g_pose[gw]);
            float fsim = dotbf(g_feat_bf + (size_t)p.x * FEA, g_feat_bf + (size_t)p.y * FEA, lane);
            float wv   = dotbf(g_rep_bf  + (size_t)p.x * HID, g_rep_bf  + (size_t)p.y * HID, lane);
            float pos = fsim * THETA + fmaxf(wv, 0.f) * (1.0f - THETA);
            float t = pos - __ldg(&g_pls[gw]);
            pos_local = t * t;
        }
    } else {
        int k = gw - EE;
        if (k < nneg) {
            int2 p = __ldg(&g_nege[k]);
            float wv = fmaxf(dotbf(g_rep_bf + (size_t)p.x * HID, g_rep_bf + (size_t)p.y * HID, lane), 0.f);
            neg_local = wv * wv;
        }
    }

    __shared__ float sp[16], sn[16];
    if (lane == 0) { sp[wid] = pos_local; sn[wid] = neg_local; }
    __syncthreads();
    if (threadIdx.x == 0) {
        double p = 0.0, q = 0.0;
#pragma unroll
        for (int k = 0; k < 16; k++) { p += sp[k]; q += sn[k]; }
        if (p != 0.0) atomicAdd(&g_pos_loss, p);
        if (q != 0.0) atomicAdd(&g_neg_loss, q);
    }
}

__global__ void k_finish_loss(float* __restrict__ out_scalar) {
    double tot = g_pos_loss + g_neg_loss;
    double denom = (double)(g_npos + g_nneg);
    out_scalar[0] = (float)(tot * (double)NN / denom);
}

// ---------------- launch ----------------
extern "C" void kernel_launch(void* const* d_in, const int* in_sizes, int n_in,
                              void* d_out, int out_size) {
    const int*   edge_index = (const int*)d_in[0];
    const float* features   = (const float*)d_in[1];
    const float* label_sm   = (const float*)d_in[2];
    const int*   neg_edge   = (const int*)d_in[3];
    const float* W1 = (const float*)d_in[4];
    const float* b1 = (const float*)d_in[5];
    const float* W2 = (const float*)d_in[6];
    const float* b2 = (const float*)d_in[7];
    const float* Wy = (const float*)d_in[8];
    const float* by = (const float*)d_in[9];

    const int* e0 = edge_index;
    const int* e1 = edge_index + EE;
    const int* n0 = neg_edge;
    const int* n1 = neg_edge + EE;

    float* rep_out  = (float*)d_out;                           // [N,256]
    float* loss_out = (float*)d_out + (size_t)NN * HID;        // [1]
    float* y_out    = loss_out + 1;                            // [N,64] 4B-aligned only

    void *p_deg, *ph, *px, *pfb;
    cudaGetSymbolAddress(&p_deg, g_deg);
    cudaGetSymbolAddress(&ph, g_h);
    cudaGetSymbolAddress(&px, g_x1);
    cudaGetSymbolAddress(&pfb, g_feat_bf);
    float* h  = (float*)ph;
    float* x1 = (float*)px;
    __nv_bfloat16* feat_bf = (__nv_bfloat16*)pfb;

    // 1. CSR build + pair compaction + feat bf16 copy
    cudaMemsetAsync(p_deg, 0, NN * sizeof(int));
    k_zero_loss<<<1, 1>>>();
    k_deg_compact<<<(EE + 255) / 256, 256>>>(e0, e1, n0, n1, label_sm);
    k_scan<<<1, 1024>>>(NN);
    k_csr_fill<<<(EE + 255) / 256, 256>>>(e0, e1, EE);
    {
        int n4 = NN * FEA / 4;
        k_f2bf<<<(n4 + 255) / 256, 256>>>(features, feat_bf, n4);
    }

    // 2. conv1: h = features @ W1 (tf32) ; gather+relu -> x1
    {
        dim3 grid(HID / 128, (NN + 127) / 128), block(256);
        k_gemm_tf32<128, true><<<grid, block>>>(features, W1, h, nullptr, NN, FEA, HID);
    }
    k_gather<0><<<NN, 256>>>(h, b1, x1);

    // 3. conv2: h = x1 @ W2 (tf32) ; gather + double l2norm -> rep (+bf16 copy)
    {
        dim3 grid(HID / 128, (NN + 127) / 128), block(256);
        k_gemm_tf32<128, true><<<grid, block>>>(x1, W2, h, nullptr, NN, HID, HID);
    }
    k_gather<1><<<NN, 256>>>(h, b2, rep_out);

    // 4. y = rep @ Wy + by (tf32; scalar stores for 4B-aligned y_out)
    {
        dim3 grid(CLS / 64, (NN + 127) / 128), block(256);
        k_gemm_tf32<64, false><<<grid, block>>>(rep_out, Wy, y_out, by, NN, HID, CLS);
    }

    // 5. loss over compacted lists (bf16 operands)
    {
        long long warps = 2LL * EE;
        int blocks = (int)((warps * 32 + 511) / 512);
        k_loss<<<blocks, 512>>>();
    }
    k_finish_loss<<<1, 1>>>(loss_out);
}

// round 14
// speedup vs baseline: 1.6994x; 1.0610x over previous
#include <cuda_runtime.h>
#include <cuda_bf16.h>
#include <math.h>

// Problem constants (static per reference).
#define NN   50000
#define EE   800000
#define FEA  256
#define HID  256
#define CLS  64
#define THETA 0.5f

// ---------------- device scratch (no allocs allowed) ----------------
__device__ int    g_deg[NN];
__device__ float  g_dinv[NN];
__device__ int    g_rowptr[NN + 1];
__device__ int    g_cursor[NN];
__device__ int    g_ecol[EE];                      // CSR column indices
__device__ float  g_h  [(size_t)NN * HID];         // fp32 h (conv2)
__device__ __nv_bfloat16 g_h_bf[(size_t)NN * HID]; // bf16 h (conv1 gather)
__device__ float  g_x1 [(size_t)NN * HID];         // relu'd conv1 output
__device__ __nv_bfloat16 g_feat_bf[(size_t)NN * FEA];  // bf16 features (loss)
__device__ __nv_bfloat16 g_rep_bf [(size_t)NN * HID];  // bf16 rep (loss)
__device__ int2   g_pose[EE];                      // compacted pos pairs (a<b)
__device__ float  g_pls [EE];                      // their label_smoothing
__device__ int2   g_nege[EE];                      // compacted neg pairs (a<b)
__device__ int    g_npos, g_nneg;
__device__ double g_pos_loss;
__device__ double g_neg_loss;

// ---------------- zero counters ----------------
__global__ void k_zero_loss() {
    g_pos_loss = 0.0; g_neg_loss = 0.0; g_npos = 0; g_nneg = 0;
}

// ---------------- fused: degree count + a<b pair compaction ----------------
__global__ void k_deg_compact(const int* __restrict__ e0, const int* __restrict__ e1,
                              const int* __restrict__ n0, const int* __restrict__ n1,
                              const float* __restrict__ ls) {
    int i = blockIdx.x * blockDim.x + threadIdx.x;
    __shared__ int scp, scn, sbp, sbn;
    if (threadIdx.x == 0) { scp = 0; scn = 0; }
    __syncthreads();
    int a = 0, b = 0, na = 0, nb = 0;
    bool vp = false, vn = false;
    int lp = 0, ln = 0;
    float lsv = 0.f;
    if (i < EE) {
        a = e0[i]; b = e1[i]; vp = a < b;
        na = n0[i]; nb = n1[i]; vn = na < nb;
        if (vp) lsv = ls[i];
        atomicAdd(&g_deg[a], 1);                   // degree over rows (e0)
    }
    if (vp) lp = atomicAdd(&scp, 1);
    if (vn) ln = atomicAdd(&scn, 1);
    __syncthreads();
    if (threadIdx.x == 0) {
        sbp = atomicAdd(&g_npos, scp);
        sbn = atomicAdd(&g_nneg, scn);
    }
    __syncthreads();
    if (vp) { int p = sbp + lp; g_pose[p] = make_int2(a, b); g_pls[p] = lsv; }
    if (vn) { int p = sbn + ln; g_nege[p] = make_int2(na, nb); }
}

// ---------------- single-block scan over g_deg -> g_rowptr, g_cursor, g_dinv ----------------
__global__ void k_scan(int n) {
    const int T = 1024;
    const int C = (NN + T - 1) / T;
    __shared__ int part[T];
    int t = threadIdx.x;
    int base = t * C;
    int local = 0;
#pragma unroll 4
    for (int j = 0; j < C; j++) {
        int idx = base + j;
        if (idx < n) local += g_deg[idx];
    }
    part[t] = local;
    __syncthreads();
    for (int off = 1; off < T; off <<= 1) {
        int v = (t >= off) ? part[t - off] : 0;
        __syncthreads();
        part[t] += v;
        __syncthreads();
    }
    int run = (t == 0) ? 0 : part[t - 1];
    for (int j = 0; j < C; j++) {
        int idx = base + j;
        if (idx < n) {
            g_rowptr[idx] = run;
            g_cursor[idx] = run;
            int d = g_deg[idx];
            run += d;
            g_dinv[idx] = rsqrtf((float)(d + 1));   // +1 self loop
        }
    }
    if (t == T - 1) g_rowptr[n] = EE;
}

// ---------------- CSR fill ----------------
__global__ void k_csr_fill(const int* __restrict__ row, const int* __restrict__ col, int e) {
    int i = blockIdx.x * blockDim.x + threadIdx.x;
    if (i >= e) return;
    int r = row[i];
    int p = atomicAdd(&g_cursor[r], 1);
    g_ecol[p] = col[i];
}

// ---------------- fp32 -> bf16 conversion (vectorized) ----------------
__global__ void k_f2bf(const float* __restrict__ src, __nv_bfloat16* __restrict__ dst,
                       int n4) {
    int i = blockIdx.x * blockDim.x + threadIdx.x;
    if (i >= n4) return;
    float4 v = ((const float4*)src)[i];
    __nv_bfloat162 lo = __float22bfloat162_rn(make_float2(v.x, v.y));
    __nv_bfloat162 hi = __float22bfloat162_rn(make_float2(v.z, v.w));
    ((__nv_bfloat162*)dst)[2 * i]     = lo;
    ((__nv_bfloat162*)dst)[2 * i + 1] = hi;
}

// ---------------- tf32 tensor-core GEMM: C[M,Nc] = A[M,K] @ B[K,Nc] (+bias) ----------------
// OUTMODE: 0 = fp32 float2 stores, 1 = fp32 scalar stores (4B-aligned dst), 2 = bf16 stores
__device__ __forceinline__ unsigned f2tf32(float f) {
    unsigned r;
    asm("cvt.rna.tf32.f32 %0, %1;" : "=r"(r) : "f"(f));
    return r;
}

template <int BN, int OUTMODE>
__global__ void __launch_bounds__(256, 2) k_gemm_tf32(const float* __restrict__ A,
                                                      const float* __restrict__ B,
                                                      void* __restrict__ Cv,
                                                      const float* __restrict__ bias,
                                                      int M, int K, int Nc) {
    constexpr int NI = BN / 16;
    constexpr int BS = BN + 4;
    __shared__ float As[128 * 36];
    __shared__ float Bs[32 * BS];

    const int tid  = threadIdx.x;
    const int wid  = tid >> 5;
    const int lane = tid & 31;
    const int g    = lane >> 2;
    const int tg   = lane & 3;
    const int warp_m = wid & 3;
    const int warp_n = wid >> 2;
    const int m_base = warp_m * 32;
    const int n_base = warp_n * (BN / 2);
    const int bm = blockIdx.y * 128;
    const int bn = blockIdx.x * BN;

    float c[2][NI][4];
#pragma unroll
    for (int mi = 0; mi < 2; mi++)
#pragma unroll
        for (int ni = 0; ni < NI; ni++)
#pragma unroll
            for (int q = 0; q < 4; q++) c[mi][ni][q] = 0.f;

    for (int k0 = 0; k0 < K; k0 += 32) {
#pragma unroll
        for (int i = 0; i < 4; i++) {
            int idx = tid + i * 256;
            int row = idx >> 3, kq = (idx & 7) * 4;
            int gm = bm + row;
            float4 v = make_float4(0.f, 0.f, 0.f, 0.f);
            if (gm < M) v = *(const float4*)(A + (size_t)gm * K + k0 + kq);
            float* dst = As + row * 36 + kq;
            dst[0] = __uint_as_float(f2tf32(v.x));
            dst[1] = __uint_as_float(f2tf32(v.y));
            dst[2] = __uint_as_float(f2tf32(v.z));
            dst[3] = __uint_as_float(f2tf32(v.w));
        }
#pragma unroll
        for (int i = 0; i < (32 * BN / 4) / 256; i++) {
            int idx = tid + i * 256;
            int row = idx / (BN / 4), c4 = (idx % (BN / 4)) * 4;
            float4 v = *(const float4*)(B + (size_t)(k0 + row) * Nc + bn + c4);
            float* dst = Bs + row * BS + c4;
            dst[0] = __uint_as_float(f2tf32(v.x));
            dst[1] = __uint_as_float(f2tf32(v.y));
            dst[2] = __uint_as_float(f2tf32(v.z));
            dst[3] = __uint_as_float(f2tf32(v.w));
        }
        __syncthreads();

#pragma unroll
        for (int kk = 0; kk < 4; kk++) {
            unsigned a[2][4], b[NI][2];
#pragma unroll
            for (int mi = 0; mi < 2; mi++) {
                int r0 = m_base + mi * 16 + g;
                a[mi][0] = __float_as_uint(As[r0 * 36 + kk * 8 + tg]);
                a[mi][1] = __float_as_uint(As[(r0 + 8) * 36 + kk * 8 + tg]);
                a[mi][2] = __float_as_uint(As[r0 * 36 + kk * 8 + tg + 4]);
                a[mi][3] = __float_as_uint(As[(r0 + 8) * 36 + kk * 8 + tg + 4]);
            }
#pragma unroll
            for (int ni = 0; ni < NI; ni++) {
                int col = n_base + ni * 8 + g;
                b[ni][0] = __float_as_uint(Bs[(kk * 8 + tg) * BS + col]);
                b[ni][1] = __float_as_uint(Bs[(kk * 8 + tg + 4) * BS + col]);
            }
#pragma unroll
            for (int mi = 0; mi < 2; mi++)
#pragma unroll
                for (int ni = 0; ni < NI; ni++) {
                    asm volatile(
                        "mma.sync.aligned.m16n8k8.row.col.f32.tf32.tf32.f32 "
                        "{%0,%1,%2,%3}, {%4,%5,%6,%7}, {%8,%9}, {%0,%1,%2,%3};"
                        : "+f"(c[mi][ni][0]), "+f"(c[mi][ni][1]),
                          "+f"(c[mi][ni][2]), "+f"(c[mi][ni][3])
                        : "r"(a[mi][0]), "r"(a[mi][1]), "r"(a[mi][2]), "r"(a[mi][3]),
                          "r"(b[ni][0]), "r"(b[ni][1]));
                }
        }
        __syncthreads();
    }

#pragma unroll
    for (int mi = 0; mi < 2; mi++) {
        int row0 = bm + m_base + mi * 16 + g;
        int row1 = row0 + 8;
#pragma unroll
        for (int ni = 0; ni < NI; ni++) {
            int col = bn + n_base + ni * 8 + 2 * tg;
            float b0 = 0.f, b1 = 0.f;
            if (bias) { b0 = bias[col]; b1 = bias[col + 1]; }
            if (OUTMODE == 0) {
                float* C = (float*)Cv;
                if (row0 < M)
                    *(float2*)(C + (size_t)row0 * Nc + col) =
                        make_float2(c[mi][ni][0] + b0, c[mi][ni][1] + b1);
                if (row1 < M)
                    *(float2*)(C + (size_t)row1 * Nc + col) =
                        make_float2(c[mi][ni][2] + b0, c[mi][ni][3] + b1);
            } else if (OUTMODE == 1) {
                float* C = (float*)Cv;
                if (row0 < M) {
                    C[(size_t)row0 * Nc + col]     = c[mi][ni][0] + b0;
                    C[(size_t)row0 * Nc + col + 1] = c[mi][ni][1] + b1;
                }
                if (row1 < M) {
                    C[(size_t)row1 * Nc + col]     = c[mi][ni][2] + b0;
                    C[(size_t)row1 * Nc + col + 1] = c[mi][ni][3] + b1;
                }
            } else {
                __nv_bfloat16* C = (__nv_bfloat16*)Cv;
                if (row0 < M)
                    *(__nv_bfloat162*)(C + (size_t)row0 * Nc + col) =
                        __float22bfloat162_rn(make_float2(c[mi][ni][0] + b0, c[mi][ni][1] + b1));
                if (row1 < M)
                    *(__nv_bfloat162*)(C + (size_t)row1 * Nc + col) =
                        __float22bfloat162_rn(make_float2(c[mi][ni][2] + b0, c[mi][ni][3] + b1));
            }
        }
    }
}

// ---------------- fused gather conv ----------------
// MODE 0: bf16 h input, relu -> fp32 out
// MODE 1: fp32 h input, double-l2norm -> fp32 out + bf16 rep copy
template <int MODE>
__global__ void __launch_bounds__(256) k_gather(const void* __restrict__ hv_in,
                                                const float* __restrict__ bias,
                                                float* __restrict__ out) {
    const int r   = blockIdx.x;
    const int tid = threadIdx.x;
    const int grp = tid >> 6;
    const int q   = tid & 63;
    const int s = g_rowptr[r];
    const int e = g_rowptr[r + 1];

    __shared__ int   sc[256];
    __shared__ float sd[256];
    __shared__ float4 red[4][64];

    float4 acc = make_float4(0.f, 0.f, 0.f, 0.f);
    for (int base = s; base < e; base += 256) {
        int nb = min(256, e - base);
        if (tid < nb) {
            int c = g_ecol[base + tid];
            sc[tid] = c;
            sd[tid] = g_dinv[c];
        }
        __syncthreads();
        for (int j = grp; j < nb; j += 4) {
            int c = sc[j];
            float d = sd[j];
            float4 v;
            if (MODE == 0) {
                const __nv_bfloat16* hb = (const __nv_bfloat16*)hv_in;
                uint2 u = __ldg((const uint2*)(hb + (size_t)c * HID) + q);
                float2 f0 = __bfloat1622float2(*(const __nv_bfloat162*)&u.x);
                float2 f1 = __bfloat1622float2(*(const __nv_bfloat162*)&u.y);
                v = make_float4(f0.x, f0.y, f1.x, f1.y);
            } else {
                const float* h = (const float*)hv_in;
                v = __ldg((const float4*)(h + (size_t)c * HID) + q);
            }
            acc.x = fmaf(d, v.x, acc.x);
            acc.y = fmaf(d, v.y, acc.y);
            acc.z = fmaf(d, v.z, acc.z);
            acc.w = fmaf(d, v.w, acc.w);
        }
        __syncthreads();
    }
    red[grp][q] = acc;
    __syncthreads();

    float4 t0 = red[0][q], t1 = red[1][q], t2 = red[2][q], t3 = red[3][q];
    float4 sum;
    sum.x = (t0.x + t1.x) + (t2.x + t3.x);
    sum.y = (t0.y + t1.y) + (t2.y + t3.y);
    sum.z = (t0.z + t1.z) + (t2.z + t3.z);
    sum.w = (t0.w + t1.w) + (t2.w + t3.w);

    const float di = g_dinv[r];
    float4 hv;
    if (MODE == 0) {
        const __nv_bfloat16* hb = (const __nv_bfloat16*)hv_in;
        uint2 u = __ldg((const uint2*)(hb + (size_t)r * HID) + q);
        float2 f0 = __bfloat1622float2(*(const __nv_bfloat162*)&u.x);
        float2 f1 = __bfloat1622float2(*(const __nv_bfloat162*)&u.y);
        hv = make_float4(f0.x, f0.y, f1.x, f1.y);
    } else {
        const float* h = (const float*)hv_in;
        hv = __ldg((const float4*)(h + (size_t)r * HID) + q);
    }
    float4 bv = __ldg((const float4*)bias + q);
    float4 v;
    v.x = di * (sum.x + di * hv.x) + bv.x;
    v.y = di * (sum.y + di * hv.y) + bv.y;
    v.z = di * (sum.z + di * hv.z) + bv.z;
    v.w = di * (sum.w + di * hv.w) + bv.w;

    if (MODE == 0) {
        if (grp == 0) {
            float4 o;
            o.x = fmaxf(v.x, 0.f); o.y = fmaxf(v.y, 0.f);
            o.z = fmaxf(v.z, 0.f); o.w = fmaxf(v.w, 0.f);
            *((float4*)(out + (size_t)r * HID) + q) = o;
        }
    } else {
        float sq = v.x * v.x + v.y * v.y + v.z * v.z + v.w * v.w;
#pragma unroll
        for (int o = 16; o; o >>= 1) sq += __shfl_xor_sync(0xffffffffu, sq, o);
        __shared__ float ws[8];
        __shared__ float total;
        int wid = tid >> 5;
        if ((tid & 31) == 0) ws[wid] = sq;
        __syncthreads();
        if (tid == 0) {
            float t = 0.f;
#pragma unroll
            for (int k = 0; k < 8; k++) t += ws[k];
            total = t * 0.25f;
        }
        __syncthreads();
        float s1 = sqrtf(total);
        float d1 = fmaxf(s1, 1e-12f);
        float s2 = s1 / d1;
        float d2 = fmaxf(s2, 1e-12f);
        float inv = 1.f / (d1 * d2);
        if (grp == 0) {
            float4 o;
            o.x = v.x * inv; o.y = v.y * inv; o.z = v.z * inv; o.w = v.w * inv;
            *((float4*)(out + (size_t)r * HID) + q) = o;
            __nv_bfloat162 lo = __float22bfloat162_rn(make_float2(o.x, o.y));
            __nv_bfloat162 hi = __float22bfloat162_rn(make_float2(o.z, o.w));
            __nv_bfloat162* dst = (__nv_bfloat162*)(g_rep_bf + (size_t)r * HID) + 2 * q;
            dst[0] = lo;
            dst[1] = hi;
        }
    }
}

// ---------------- loss over compacted, densely-packed lists (bf16 operands) ----------------
__device__ __forceinline__ float dotbf(const __nv_bfloat16* __restrict__ a,
                                       const __nv_bfloat16* __restrict__ b, int lane) {
    uint4 x = __ldg((const uint4*)a + lane);
    uint4 y = __ldg((const uint4*)b + lane);
    float s = 0.f;
    const unsigned* xs = (const unsigned*)&x;
    const unsigned* ys = (const unsigned*)&y;
#pragma unroll
    for (int j = 0; j < 4; j++) {
        float2 fx = __bfloat1622float2(*(const __nv_bfloat162*)&xs[j]);
        float2 fy = __bfloat1622float2(*(const __nv_bfloat162*)&ys[j]);
        s = fmaf(fx.x, fy.x, s);
        s = fmaf(fx.y, fy.y, s);
    }
#pragma unroll
    for (int o = 16; o; o >>= 1) s += __shfl_xor_sync(0xffffffffu, s, o);
    return s;
}

__global__ void k_loss(void) {
    const int npos = g_npos;
    const int total = npos + g_nneg;
    const int wpb = blockDim.x >> 5;
    const int gw0 = blockIdx.x * wpb;
    if (gw0 >= total) return;                       // fully-idle block: exit early

    int gw = gw0 + (threadIdx.x >> 5);
    int lane = threadIdx.x & 31;
    int wid = threadIdx.x >> 5;

    float pos_local = 0.f, neg_local = 0.f;
    if (gw < npos) {
        int2 p = __ldg(&g_pose[gw]);
        float fsim = dotbf(g_feat_bf + (size_t)p.x * FEA, g_feat_bf + (size_t)p.y * FEA, lane);
        float wv   = dotbf(g_rep_bf  + (size_t)p.x * HID, g_rep_bf  + (size_t)p.y * HID, lane);
        float pos = fsim * THETA + fmaxf(wv, 0.f) * (1.0f - THETA);
        float t = pos - __ldg(&g_pls[gw]);
        pos_local = t * t;
    } else if (gw < total) {
        int k = gw - npos;
        int2 p = __ldg(&g_nege[k]);
        float wv = fmaxf(dotbf(g_rep_bf + (size_t)p.x * HID, g_rep_bf + (size_t)p.y * HID, lane), 0.f);
        neg_local = wv * wv;
    }

    __shared__ float sp[16], sn[16];
    if (lane == 0) { sp[wid] = pos_local; sn[wid] = neg_local; }
    __syncthreads();
    if (threadIdx.x == 0) {
        double p = 0.0, q = 0.0;
#pragma unroll
        for (int k = 0; k < 16; k++) { p += sp[k]; q += sn[k]; }
        if (p != 0.0) atomicAdd(&g_pos_loss, p);
        if (q != 0.0) atomicAdd(&g_neg_loss, q);
    }
}

__global__ void k_finish_loss(float* __restrict__ out_scalar) {
    double tot = g_pos_loss + g_neg_loss;
    double denom = (double)(g_npos + g_nneg);
    out_scalar[0] = (float)(tot * (double)NN / denom);
}

// ---------------- launch ----------------
extern "C" void kernel_launch(void* const* d_in, const int* in_sizes, int n_in,
                              void* d_out, int out_size) {
    const int*   edge_index = (const int*)d_in[0];
    const float* features   = (const float*)d_in[1];
    const float* label_sm   = (const float*)d_in[2];
    const int*   neg_edge   = (const int*)d_in[3];
    const float* W1 = (const float*)d_in[4];
    const float* b1 = (const float*)d_in[5];
    const float* W2 = (const float*)d_in[6];
    const float* b2 = (const float*)d_in[7];
    const float* Wy = (const float*)d_in[8];
    const float* by = (const float*)d_in[9];

    const int* e0 = edge_index;
    const int* e1 = edge_index + EE;
    const int* n0 = neg_edge;
    const int* n1 = neg_edge + EE;

    float* rep_out  = (float*)d_out;                           // [N,256]
    float* loss_out = (float*)d_out + (size_t)NN * HID;        // [1]
    float* y_out    = loss_out + 1;                            // [N,64] 4B-aligned only

    void *p_deg, *ph, *phb, *px, *pfb;
    cudaGetSymbolAddress(&p_deg, g_deg);
    cudaGetSymbolAddress(&ph, g_h);
    cudaGetSymbolAddress(&phb, g_h_bf);
    cudaGetSymbolAddress(&px, g_x1);
    cudaGetSymbolAddress(&pfb, g_feat_bf);
    float* h  = (float*)ph;
    __nv_bfloat16* h_bf = (__nv_bfloat16*)phb;
    float* x1 = (float*)px;
    __nv_bfloat16* feat_bf = (__nv_bfloat16*)pfb;

    // 1. CSR build + pair compaction + feat bf16 copy
    cudaMemsetAsync(p_deg, 0, NN * sizeof(int));
    k_zero_loss<<<1, 1>>>();
    k_deg_compact<<<(EE + 255) / 256, 256>>>(e0, e1, n0, n1, label_sm);
    k_scan<<<1, 1024>>>(NN);
    k_csr_fill<<<(EE + 255) / 256, 256>>>(e0, e1, EE);
    {
        int n4 = NN * FEA / 4;
        k_f2bf<<<(n4 + 255) / 256, 256>>>(features, feat_bf, n4);
    }

    // 2. conv1: h_bf = features @ W1 (tf32, bf16 out) ; gather(bf16)+relu -> x1
    {
        dim3 grid(HID / 128, (NN + 127) / 128), block(256);
        k_gemm_tf32<128, 2><<<grid, block>>>(features, W1, h_bf, nullptr, NN, FEA, HID);
    }
    k_gather<0><<<NN, 256>>>(h_bf, b1, x1);

    // 3. conv2: h = x1 @ W2 (tf32, fp32 out) ; gather(fp32) + double l2norm -> rep (+bf16)
    {
        dim3 grid(HID / 128, (NN + 127) / 128), block(256);
        k_gemm_tf32<128, 0><<<grid, block>>>(x1, W2, h, nullptr, NN, HID, HID);
    }
    k_gather<1><<<NN, 256>>>(h, b2, rep_out);

    // 4. y = rep @ Wy + by (tf32; scalar stores for 4B-aligned y_out)
    {
        dim3 grid(CLS / 64, (NN + 127) / 128), block(256);
        k_gemm_tf32<64, 1><<<grid, block>>>(rep_out, Wy, y_out, by, NN, HID, CLS);
    }

    // 5. loss over densely-packed compacted lists
    {
        long long warps = 2LL * EE;                  // upper bound; blocks early-exit
        int blocks = (int)((warps * 32 + 511) / 512);
        k_loss<<<blocks, 512>>>();
    }
    k_finish_loss<<<1, 1>>>(loss_out);
}

// round 17
// speedup vs baseline: 1.9762x; 1.1629x over previous
#include <cuda_runtime.h>
#include <cuda_bf16.h>
#include <math.h>

// Problem constants (static per reference).
#define NN   50000
#define EE   800000
#define FEA  256
#define HID  256
#define CLS  64
#define THETA 0.5f

// ---------------- device scratch (no allocs allowed) ----------------
__device__ int    g_deg[NN];
__device__ float  g_dinv[NN];
__device__ int    g_rowptr[NN + 1];
__device__ int    g_cursor[NN];
__device__ int    g_ecol[EE];                      // CSR column indices
__device__ float  g_h  [(size_t)NN * HID];         // fp32 h (conv2)
__device__ __nv_bfloat16 g_h_bf[(size_t)NN * HID]; // bf16 h (conv1 gather)
__device__ float  g_x1 [(size_t)NN * HID];         // relu'd conv1 output
__device__ __nv_bfloat16 g_feat_bf[(size_t)NN * FEA];  // bf16 features (loss)
__device__ __nv_bfloat16 g_rep_bf [(size_t)NN * HID];  // bf16 rep (loss)
__device__ int2   g_pose[EE];                      // compacted pos pairs (a<b)
__device__ float  g_pls [EE];                      // their label_smoothing
__device__ int2   g_nege[EE];                      // compacted neg pairs (a<b)

struct LossState {
    int npos;
    int nneg;
    double pos_loss;
    double neg_loss;
};
__device__ LossState g_ls;                         // zeroed via one memset

// ---------------- fused: degree count + a<b pair compaction + feat->bf16 ----------------
__global__ void k_deg_compact(const int* __restrict__ e0, const int* __restrict__ e1,
                              const int* __restrict__ n0, const int* __restrict__ n1,
                              const float* __restrict__ ls,
                              const float* __restrict__ feat) {
    int i = blockIdx.x * blockDim.x + threadIdx.x;
    __shared__ int scp, scn, sbp, sbn;
    if (threadIdx.x == 0) { scp = 0; scn = 0; }
    __syncthreads();
    int a = 0, b = 0, na = 0, nb = 0;
    bool vp = false, vn = false;
    int lp = 0, ln = 0;
    float lsv = 0.f;
    if (i < EE) {
        a = e0[i]; b = e1[i]; vp = a < b;
        na = n0[i]; nb = n1[i]; vn = na < nb;
        if (vp) lsv = ls[i];
        atomicAdd(&g_deg[a], 1);                   // degree over rows (e0)
        // fused feat -> bf16 conversion: 4 float4s per thread, coalesced strided
#pragma unroll
        for (int k = 0; k < 4; k++) {
            int idx = i + k * EE;                  // 0 .. 3.2M-1 = NN*FEA/4
            float4 v = ((const float4*)feat)[idx];
            __nv_bfloat162 lo = __float22bfloat162_rn(make_float2(v.x, v.y));
            __nv_bfloat162 hi = __float22bfloat162_rn(make_float2(v.z, v.w));
            ((__nv_bfloat162*)g_feat_bf)[2 * idx]     = lo;
            ((__nv_bfloat162*)g_feat_bf)[2 * idx + 1] = hi;
        }
    }
    if (vp) lp = atomicAdd(&scp, 1);
    if (vn) ln = atomicAdd(&scn, 1);
    __syncthreads();
    if (threadIdx.x == 0) {
        sbp = atomicAdd(&g_ls.npos, scp);
        sbn = atomicAdd(&g_ls.nneg, scn);
    }
    __syncthreads();
    if (vp) { int p = sbp + lp; g_pose[p] = make_int2(a, b); g_pls[p] = lsv; }
    if (vn) { int p = sbn + ln; g_nege[p] = make_int2(na, nb); }
}

// ---------------- single-block scan over g_deg -> g_rowptr, g_cursor, g_dinv ----------------
__global__ void k_scan(int n) {
    const int T = 1024;
    const int C = (NN + T - 1) / T;
    __shared__ int part[T];
    int t = threadIdx.x;
    int base = t * C;
    int local = 0;
#pragma unroll 4
    for (int j = 0; j < C; j++) {
        int idx = base + j;
        if (idx < n) local += g_deg[idx];
    }
    part[t] = local;
    __syncthreads();
    for (int off = 1; off < T; off <<= 1) {
        int v = (t >= off) ? part[t - off] : 0;
        __syncthreads();
        part[t] += v;
        __syncthreads();
    }
    int run = (t == 0) ? 0 : part[t - 1];
    for (int j = 0; j < C; j++) {
        int idx = base + j;
        if (idx < n) {
            g_rowptr[idx] = run;
            g_cursor[idx] = run;
            int d = g_deg[idx];
            run += d;
            g_dinv[idx] = rsqrtf((float)(d + 1));   // +1 self loop
        }
    }
    if (t == T - 1) g_rowptr[n] = EE;
}

// ---------------- CSR fill ----------------
__global__ void k_csr_fill(const int* __restrict__ row, const int* __restrict__ col, int e) {
    int i = blockIdx.x * blockDim.x + threadIdx.x;
    if (i >= e) return;
    int r = row[i];
    int p = atomicAdd(&g_cursor[r], 1);
    g_ecol[p] = col[i];
}

// ---------------- tf32 tensor-core GEMM: C[M,Nc] = A[M,K] @ B[K,Nc] (+bias) ----------------
// OUTMODE: 0 = fp32 float2 stores, 1 = fp32 scalar stores (4B-aligned dst), 2 = bf16 stores
__device__ __forceinline__ unsigned f2tf32(float f) {
    unsigned r;
    asm("cvt.rna.tf32.f32 %0, %1;" : "=r"(r) : "f"(f));
    return r;
}

template <int BN, int OUTMODE>
__global__ void __launch_bounds__(256, 2) k_gemm_tf32(const float* __restrict__ A,
                                                      const float* __restrict__ B,
                                                      void* __restrict__ Cv,
                                                      const float* __restrict__ bias,
                                                      int M, int K, int Nc) {
    constexpr int NI = BN / 16;
    constexpr int BS = BN + 4;
    __shared__ float As[128 * 36];
    __shared__ float Bs[32 * BS];

    const int tid  = threadIdx.x;
    const int wid  = tid >> 5;
    const int lane = tid & 31;
    const int g    = lane >> 2;
    const int tg   = lane & 3;
    const int warp_m = wid & 3;
    const int warp_n = wid >> 2;
    const int m_base = warp_m * 32;
    const int n_base = warp_n * (BN / 2);
    const int bm = blockIdx.y * 128;
    const int bn = blockIdx.x * BN;

    float c[2][NI][4];
#pragma unroll
    for (int mi = 0; mi < 2; mi++)
#pragma unroll
        for (int ni = 0; ni < NI; ni++)
#pragma unroll
            for (int q = 0; q < 4; q++) c[mi][ni][q] = 0.f;

    for (int k0 = 0; k0 < K; k0 += 32) {
#pragma unroll
        for (int i = 0; i < 4; i++) {
            int idx = tid + i * 256;
            int row = idx >> 3, kq = (idx & 7) * 4;
            int gm = bm + row;
            float4 v = make_float4(0.f, 0.f, 0.f, 0.f);
            if (gm < M) v = *(const float4*)(A + (size_t)gm * K + k0 + kq);
            float* dst = As + row * 36 + kq;
            dst[0] = __uint_as_float(f2tf32(v.x));
            dst[1] = __uint_as_float(f2tf32(v.y));
            dst[2] = __uint_as_float(f2tf32(v.z));
            dst[3] = __uint_as_float(f2tf32(v.w));
        }
#pragma unroll
        for (int i = 0; i < (32 * BN / 4) / 256; i++) {
            int idx = tid + i * 256;
            int row = idx / (BN / 4), c4 = (idx % (BN / 4)) * 4;
            float4 v = *(const float4*)(B + (size_t)(k0 + row) * Nc + bn + c4);
            float* dst = Bs + row * BS + c4;
            dst[0] = __uint_as_float(f2tf32(v.x));
            dst[1] = __uint_as_float(f2tf32(v.y));
            dst[2] = __uint_as_float(f2tf32(v.z));
            dst[3] = __uint_as_float(f2tf32(v.w));
        }
        __syncthreads();

#pragma unroll
        for (int kk = 0; kk < 4; kk++) {
            unsigned a[2][4], b[NI][2];
#pragma unroll
            for (int mi = 0; mi < 2; mi++) {
                int r0 = m_base + mi * 16 + g;
                a[mi][0] = __float_as_uint(As[r0 * 36 + kk * 8 + tg]);
                a[mi][1] = __float_as_uint(As[(r0 + 8) * 36 + kk * 8 + tg]);
                a[mi][2] = __float_as_uint(As[r0 * 36 + kk * 8 + tg + 4]);
                a[mi][3] = __float_as_uint(As[(r0 + 8) * 36 + kk * 8 + tg + 4]);
            }
#pragma unroll
            for (int ni = 0; ni < NI; ni++) {
                int col = n_base + ni * 8 + g;
                b[ni][0] = __float_as_uint(Bs[(kk * 8 + tg) * BS + col]);
                b[ni][1] = __float_as_uint(Bs[(kk * 8 + tg + 4) * BS + col]);
            }
#pragma unroll
            for (int mi = 0; mi < 2; mi++)
#pragma unroll
                for (int ni = 0; ni < NI; ni++) {
                    asm volatile(
                        "mma.sync.aligned.m16n8k8.row.col.f32.tf32.tf32.f32 "
                        "{%0,%1,%2,%3}, {%4,%5,%6,%7}, {%8,%9}, {%0,%1,%2,%3};"
                        : "+f"(c[mi][ni][0]), "+f"(c[mi][ni][1]),
                          "+f"(c[mi][ni][2]), "+f"(c[mi][ni][3])
                        : "r"(a[mi][0]), "r"(a[mi][1]), "r"(a[mi][2]), "r"(a[mi][3]),
                          "r"(b[ni][0]), "r"(b[ni][1]));
                }
        }
        __syncthreads();
    }

#pragma unroll
    for (int mi = 0; mi < 2; mi++) {
        int row0 = bm + m_base + mi * 16 + g;
        int row1 = row0 + 8;
#pragma unroll
        for (int ni = 0; ni < NI; ni++) {
            int col = bn + n_base + ni * 8 + 2 * tg;
            float b0 = 0.f, b1 = 0.f;
            if (bias) { b0 = bias[col]; b1 = bias[col + 1]; }
            if (OUTMODE == 0) {
                float* C = (float*)Cv;
                if (row0 < M)
                    *(float2*)(C + (size_t)row0 * Nc + col) =
                        make_float2(c[mi][ni][0] + b0, c[mi][ni][1] + b1);
                if (row1 < M)
                    *(float2*)(C + (size_t)row1 * Nc + col) =
                        make_float2(c[mi][ni][2] + b0, c[mi][ni][3] + b1);
            } else if (OUTMODE == 1) {
                float* C = (float*)Cv;
                if (row0 < M) {
                    C[(size_t)row0 * Nc + col]     = c[mi][ni][0] + b0;
                    C[(size_t)row0 * Nc + col + 1] = c[mi][ni][1] + b1;
                }
                if (row1 < M) {
                    C[(size_t)row1 * Nc + col]     = c[mi][ni][2] + b0;
                    C[(size_t)row1 * Nc + col + 1] = c[mi][ni][3] + b1;
                }
            } else {
                __nv_bfloat16* C = (__nv_bfloat16*)Cv;
                if (row0 < M)
                    *(__nv_bfloat162*)(C + (size_t)row0 * Nc + col) =
                        __float22bfloat162_rn(make_float2(c[mi][ni][0] + b0, c[mi][ni][1] + b1));
                if (row1 < M)
                    *(__nv_bfloat162*)(C + (size_t)row1 * Nc + col) =
                        __float22bfloat162_rn(make_float2(c[mi][ni][2] + b0, c[mi][ni][3] + b1));
            }
        }
    }
}

// ---------------- fused gather conv: 4 nodes per block, 64 threads per node ----------------
// MODE 0: bf16 h input, relu -> fp32 out
// MODE 1: fp32 h input, double-l2norm -> fp32 out + bf16 rep copy
template <int MODE>
__global__ void __launch_bounds__(256) k_gather(const void* __restrict__ hv_in,
                                                const float* __restrict__ bias,
                                                float* __restrict__ out) {
    const int tid = threadIdx.x;
    const int nl  = tid >> 6;                       // node slot 0..3
    const int q   = tid & 63;                       // feature quad
    const int r   = blockIdx.x * 4 + nl;            // NN divisible by 4
    const int s = g_rowptr[r];
    const int e = g_rowptr[r + 1];

    float4 acc0 = make_float4(0.f, 0.f, 0.f, 0.f);
    float4 acc1 = make_float4(0.f, 0.f, 0.f, 0.f);

    int j = s;
    for (; j + 1 < e; j += 2) {
        int c0 = __ldg(&g_ecol[j]);
        int c1 = __ldg(&g_ecol[j + 1]);
        float d0 = __ldg(&g_dinv[c0]);
        float d1 = __ldg(&g_dinv[c1]);
        float4 v0, v1;
        if (MODE == 0) {
            const __nv_bfloat16* hb = (const __nv_bfloat16*)hv_in;
            uint2 u0 = __ldg((const uint2*)(hb + (size_t)c0 * HID) + q);
            uint2 u1 = __ldg((const uint2*)(hb + (size_t)c1 * HID) + q);
            float2 a0 = __bfloat1622float2(*(const __nv_bfloat162*)&u0.x);
            float2 b0 = __bfloat1622float2(*(const __nv_bfloat162*)&u0.y);
            float2 a1 = __bfloat1622float2(*(const __nv_bfloat162*)&u1.x);
            float2 b1 = __bfloat1622float2(*(const __nv_bfloat162*)&u1.y);
            v0 = make_float4(a0.x, a0.y, b0.x, b0.y);
            v1 = make_float4(a1.x, a1.y, b1.x, b1.y);
        } else {
            const float* h = (const float*)hv_in;
            v0 = __ldg((const float4*)(h + (size_t)c0 * HID) + q);
            v1 = __ldg((const float4*)(h + (size_t)c1 * HID) + q);
        }
        acc0.x = fmaf(d0, v0.x, acc0.x); acc1.x = fmaf(d1, v1.x, acc1.x);
        acc0.y = fmaf(d0, v0.y, acc0.y); acc1.y = fmaf(d1, v1.y, acc1.y);
        acc0.z = fmaf(d0, v0.z, acc0.z); acc1.z = fmaf(d1, v1.z, acc1.z);
        acc0.w = fmaf(d0, v0.w, acc0.w); acc1.w = fmaf(d1, v1.w, acc1.w);
    }
    if (j < e) {
        int c0 = __ldg(&g_ecol[j]);
        float d0 = __ldg(&g_dinv[c0]);
        float4 v0;
        if (MODE == 0) {
            const __nv_bfloat16* hb = (const __nv_bfloat16*)hv_in;
            uint2 u0 = __ldg((const uint2*)(hb + (size_t)c0 * HID) + q);
            float2 a0 = __bfloat1622float2(*(const __nv_bfloat162*)&u0.x);
            float2 b0 = __bfloat1622float2(*(const __nv_bfloat162*)&u0.y);
            v0 = make_float4(a0.x, a0.y, b0.x, b0.y);
        } else {
            const float* h = (const float*)hv_in;
            v0 = __ldg((const float4*)(h + (size_t)c0 * HID) + q);
        }
        acc0.x = fmaf(d0, v0.x, acc0.x);
        acc0.y = fmaf(d0, v0.y, acc0.y);
        acc0.z = fmaf(d0, v0.z, acc0.z);
        acc0.w = fmaf(d0, v0.w, acc0.w);
    }

    float4 sum;
    sum.x = acc0.x + acc1.x;
    sum.y = acc0.y + acc1.y;
    sum.z = acc0.z + acc1.z;
    sum.w = acc0.w + acc1.w;

    const float di = g_dinv[r];
    float4 hv;
    if (MODE == 0) {
        const __nv_bfloat16* hb = (const __nv_bfloat16*)hv_in;
        uint2 u = __ldg((const uint2*)(hb + (size_t)r * HID) + q);
        float2 f0 = __bfloat1622float2(*(const __nv_bfloat162*)&u.x);
        float2 f1 = __bfloat1622float2(*(const __nv_bfloat162*)&u.y);
        hv = make_float4(f0.x, f0.y, f1.x, f1.y);
    } else {
        const float* h = (const float*)hv_in;
        hv = __ldg((const float4*)(h + (size_t)r * HID) + q);
    }
    float4 bv = __ldg((const float4*)bias + q);
    float4 v;
    v.x = di * (sum.x + di * hv.x) + bv.x;
    v.y = di * (sum.y + di * hv.y) + bv.y;
    v.z = di * (sum.z + di * hv.z) + bv.z;
    v.w = di * (sum.w + di * hv.w) + bv.w;

    if (MODE == 0) {
        float4 o;
        o.x = fmaxf(v.x, 0.f); o.y = fmaxf(v.y, 0.f);
        o.z = fmaxf(v.z, 0.f); o.w = fmaxf(v.w, 0.f);
        *((float4*)(out + (size_t)r * HID) + q) = o;
    } else {
        // per-node reduction across 2 warps (8 warps per block)
        float sq = v.x * v.x + v.y * v.y + v.z * v.z + v.w * v.w;
#pragma unroll
        for (int o = 16; o; o >>= 1) sq += __shfl_xor_sync(0xffffffffu, sq, o);
        __shared__ float ws[8];
        int wid = tid >> 5;
        if ((tid & 31) == 0) ws[wid] = sq;
        __syncthreads();
        float total = ws[2 * nl] + ws[2 * nl + 1];
        float s1 = sqrtf(total);
        float d1 = fmaxf(s1, 1e-12f);
        float s2 = s1 / d1;
        float d2 = fmaxf(s2, 1e-12f);
        float inv = 1.f / (d1 * d2);
        float4 o;
        o.x = v.x * inv; o.y = v.y * inv; o.z = v.z * inv; o.w = v.w * inv;
        *((float4*)(out + (size_t)r * HID) + q) = o;
        __nv_bfloat162 lo = __float22bfloat162_rn(make_float2(o.x, o.y));
        __nv_bfloat162 hi = __float22bfloat162_rn(make_float2(o.z, o.w));
        __nv_bfloat162* dst = (__nv_bfloat162*)(g_rep_bf + (size_t)r * HID) + 2 * q;
        dst[0] = lo;
        dst[1] = hi;
    }
}

// ---------------- loss over compacted, densely-packed lists (bf16 operands) ----------------
__device__ __forceinline__ float dotbf(const __nv_bfloat16* __restrict__ a,
                                       const __nv_bfloat16* __restrict__ b, int lane) {
    uint4 x = __ldg((const uint4*)a + lane);
    uint4 y = __ldg((const uint4*)b + lane);
    float s = 0.f;
    const unsigned* xs = (const unsigned*)&x;
    const unsigned* ys = (const unsigned*)&y;
#pragma unroll
    for (int j = 0; j < 4; j++) {
        float2 fx = __bfloat1622float2(*(const __nv_bfloat162*)&xs[j]);
        float2 fy = __bfloat1622float2(*(const __nv_bfloat162*)&ys[j]);
        s = fmaf(fx.x, fy.x, s);
        s = fmaf(fx.y, fy.y, s);
    }
#pragma unroll
    for (int o = 16; o; o >>= 1) s += __shfl_xor_sync(0xffffffffu, s, o);
    return s;
}

__global__ void k_loss(void) {
    const int npos = g_ls.npos;
    const int total = npos + g_ls.nneg;
    const int wpb = blockDim.x >> 5;
    const int gw0 = blockIdx.x * wpb;
    if (gw0 >= total) return;                       // fully-idle block: exit early

    int gw = gw0 + (threadIdx.x >> 5);
    int lane = threadIdx.x & 31;
    int wid = threadIdx.x >> 5;

    float pos_local = 0.f, neg_local = 0.f;
    if (gw < npos) {
        int2 p = __ldg(&g_pose[gw]);
        float fsim = dotbf(g_feat_bf + (size_t)p.x * FEA, g_feat_bf + (size_t)p.y * FEA, lane);
        float wv   = dotbf(g_rep_bf  + (size_t)p.x * HID, g_rep_bf  + (size_t)p.y * HID, lane);
        float pos = fsim * THETA + fmaxf(wv, 0.f) * (1.0f - THETA);
        float t = pos - __ldg(&g_pls[gw]);
        pos_local = t * t;
    } else if (gw < total) {
        int k = gw - npos;
        int2 p = __ldg(&g_nege[k]);
        float wv = fmaxf(dotbf(g_rep_bf + (size_t)p.x * HID, g_rep_bf + (size_t)p.y * HID, lane), 0.f);
        neg_local = wv * wv;
    }

    __shared__ float sp[16], sn[16];
    if (lane == 0) { sp[wid] = pos_local; sn[wid] = neg_local; }
    __syncthreads();
    if (threadIdx.x == 0) {
        double p = 0.0, q = 0.0;
#pragma unroll
        for (int k = 0; k < 16; k++) { p += sp[k]; q += sn[k]; }
        if (p != 0.0) atomicAdd(&g_ls.pos_loss, p);
        if (q != 0.0) atomicAdd(&g_ls.neg_loss, q);
    }
}

__global__ void k_finish_loss(float* __restrict__ out_scalar) {
    double tot = g_ls.pos_loss + g_ls.neg_loss;
    double denom = (double)(g_ls.npos + g_ls.nneg);
    out_scalar[0] = (float)(tot * (double)NN / denom);
}

// ---------------- launch ----------------
extern "C" void kernel_launch(void* const* d_in, const int* in_sizes, int n_in,
                              void* d_out, int out_size) {
    const int*   edge_index = (const int*)d_in[0];
    const float* features   = (const float*)d_in[1];
    const float* label_sm   = (const float*)d_in[2];
    const int*   neg_edge   = (const int*)d_in[3];
    const float* W1 = (const float*)d_in[4];
    const float* b1 = (const float*)d_in[5];
    const float* W2 = (const float*)d_in[6];
    const float* b2 = (const float*)d_in[7];
    const float* Wy = (const float*)d_in[8];
    const float* by = (const float*)d_in[9];

    const int* e0 = edge_index;
    const int* e1 = edge_index + EE;
    const int* n0 = neg_edge;
    const int* n1 = neg_edge + EE;

    float* rep_out  = (float*)d_out;                           // [N,256]
    float* loss_out = (float*)d_out + (size_t)NN * HID;        // [1]
    float* y_out    = loss_out + 1;                            // [N,64] 4B-aligned only

    void *p_deg, *ph, *phb, *px, *pls;
    cudaGetSymbolAddress(&p_deg, g_deg);
    cudaGetSymbolAddress(&ph, g_h);
    cudaGetSymbolAddress(&phb, g_h_bf);
    cudaGetSymbolAddress(&px, g_x1);
    cudaGetSymbolAddress(&pls, g_ls);
    float* h  = (float*)ph;
    __nv_bfloat16* h_bf = (__nv_bfloat16*)phb;
    float* x1 = (float*)px;

    // 1. CSR build + pair compaction + feat bf16 copy (fused)
    cudaMemsetAsync(p_deg, 0, NN * sizeof(int));
    cudaMemsetAsync(pls, 0, sizeof(LossState));
    k_deg_compact<<<(EE + 255) / 256, 256>>>(e0, e1, n0, n1, label_sm, features);
    k_scan<<<1, 1024>>>(NN);
    k_csr_fill<<<(EE + 255) / 256, 256>>>(e0, e1, EE);

    // 2. conv1: h_bf = features @ W1 (tf32, bf16 out) ; gather(bf16)+relu -> x1
    {
        dim3 grid(HID / 128, (NN + 127) / 128), block(256);
        k_gemm_tf32<128, 2><<<grid, block>>>(features, W1, h_bf, nullptr, NN, FEA, HID);
    }
    k_gather<0><<<NN / 4, 256>>>(h_bf, b1, x1);

    // 3. conv2: h = x1 @ W2 (tf32, fp32 out) ; gather(fp32) + double l2norm -> rep (+bf16)
    {
        dim3 grid(HID / 128, (NN + 127) / 128), block(256);
        k_gemm_tf32<128, 0><<<grid, block>>>(x1, W2, h, nullptr, NN, HID, HID);
    }
    k_gather<1><<<NN / 4, 256>>>(h, b2, rep_out);

    // 4. y = rep @ Wy + by (tf32; scalar stores for 4B-aligned y_out)
    {
        dim3 grid(CLS / 64, (NN + 127) / 128), block(256);
        k_gemm_tf32<64, 1><<<grid, block>>>(rep_out, Wy, y_out, by, NN, HID, CLS);
    }

    // 5. loss over densely-packed compacted lists
    {
        long long warps = 2LL * EE;                  // upper bound; blocks early-exit
        int blocks = (int)((warps * 32 + 511) / 512);
        k_loss<<<blocks, 512>>>();
    }
    k_finish_loss<<<1, 1>>>(loss_out);
}